// round 4
// baseline (speedup 1.0000x reference)
#include <cuda_runtime.h>
#include <cuda_bf16.h>
#include <stdint.h>

#define NPIX 6400
#define IMGW 80
#define CIN 256
#define CK 128
#define CV 256
#define QT 64
#define KT 128

// ---------------- scratch ----------------
__device__ __nv_bfloat16 g_xT[(size_t)2 * NPIX * CIN];  // [b][n][c]
__device__ __nv_bfloat16 g_Kb[(size_t)2 * NPIX * CK];   // [b][n][c]
__device__ __nv_bfloat16 g_V[(size_t)2 * NPIX * CV];    // [b][n][c]
__device__ float g_ctx[(size_t)2 * NPIX * CV];          // [b][n][c]
__device__ float g_kbias[CK];
__device__ __nv_bfloat16 g_wkb[CK * CIN];
__device__ __nv_bfloat16 g_wvb[9 * CV * CIN];

// ---------------- PTX helpers ----------------
__device__ __forceinline__ uint32_t smem_u32(const void* p) {
    uint32_t a;
    asm("{ .reg .u64 t; cvta.to.shared.u64 t, %1; cvt.u32.u64 %0, t; }" : "=r"(a) : "l"(p));
    return a;
}
__device__ __forceinline__ void ldsm4(uint32_t* r, uint32_t addr) {
    asm volatile("ldmatrix.sync.aligned.m8n8.x4.shared.b16 {%0,%1,%2,%3}, [%4];"
                 : "=r"(r[0]), "=r"(r[1]), "=r"(r[2]), "=r"(r[3]) : "r"(addr));
}
__device__ __forceinline__ void ldsm4t(uint32_t* r, uint32_t addr) {
    asm volatile("ldmatrix.sync.aligned.m8n8.x4.trans.shared.b16 {%0,%1,%2,%3}, [%4];"
                 : "=r"(r[0]), "=r"(r[1]), "=r"(r[2]), "=r"(r[3]) : "r"(addr));
}
__device__ __forceinline__ void mma_bf16(float* c, const uint32_t* a, uint32_t b0, uint32_t b1) {
    asm volatile("mma.sync.aligned.m16n8k16.row.col.f32.bf16.bf16.f32 "
                 "{%0,%1,%2,%3}, {%4,%5,%6,%7}, {%8,%9}, {%0,%1,%2,%3};"
                 : "+f"(c[0]), "+f"(c[1]), "+f"(c[2]), "+f"(c[3])
                 : "r"(a[0]), "r"(a[1]), "r"(a[2]), "r"(a[3]), "r"(b0), "r"(b1));
}
__device__ __forceinline__ void cpa16(uint32_t dst, const void* src, int sz) {
    asm volatile("cp.async.cg.shared.global [%0], [%1], 16, %2;"
                 :: "r"(dst), "l"(src), "r"(sz));
}
#define CP_COMMIT() asm volatile("cp.async.commit_group;" ::: "memory")
#define CP_WAIT(n)  asm volatile("cp.async.wait_group %0;" :: "n"(n) : "memory")

// ---------------- weight prep ----------------
__global__ void prep_kernel(const float* __restrict__ wk, const float* __restrict__ bk,
                            const float* __restrict__ gamma, const float* __restrict__ beta,
                            const float* __restrict__ rmean, const float* __restrict__ rvar,
                            const float* __restrict__ wv) {
    int tid = blockIdx.x * blockDim.x + threadIdx.x;
    int nth = gridDim.x * blockDim.x;
    if (tid < CK) {
        float inv = gamma[tid] * rsqrtf(rvar[tid] + 1e-5f);
        g_kbias[tid] = bk[tid] * inv + beta[tid] - rmean[tid] * inv;
    }
    for (int idx = tid; idx < CK * CIN; idx += nth) {
        int c = idx / CIN;
        float inv = gamma[c] * rsqrtf(rvar[c] + 1e-5f);
        g_wkb[idx] = __float2bfloat16(wk[idx] * inv);
    }
    for (int idx = tid; idx < 9 * CV * CIN; idx += nth) {
        int t = idx / (CV * CIN);
        int rem = idx - t * CV * CIN;
        int o = rem / CIN;
        int i = rem - o * CIN;
        g_wvb[idx] = __float2bfloat16(wv[(o * CIN + i) * 9 + t]);
    }
}

// ---------------- x transpose: [b][c][n] fp32 -> [b][n][c] bf16 -------------------
__global__ void transpose_x_kernel(const float* __restrict__ x) {
    __shared__ float t[32][33];
    int b = blockIdx.z, n0 = blockIdx.x * 32, c0 = blockIdx.y * 32;
    int tid = threadIdx.x, nl = tid & 31, cg = tid >> 5;
#pragma unroll
    for (int i = 0; i < 4; i++) {
        int c = cg + i * 8;
        t[c][nl] = x[((size_t)b * CIN + c0 + c) * NPIX + n0 + nl];
    }
    __syncthreads();
    __nv_bfloat162 h0 = __floats2bfloat162_rn(t[cg * 4 + 0][nl], t[cg * 4 + 1][nl]);
    __nv_bfloat162 h1 = __floats2bfloat162_rn(t[cg * 4 + 2][nl], t[cg * 4 + 3][nl]);
    uint2 v;
    v.x = *(uint32_t*)&h0; v.y = *(uint32_t*)&h1;
    *(uint2*)(g_xT + ((size_t)b * NPIX + n0 + nl) * CIN + c0 + cg * 4) = v;
}

// ---------------- conv as implicit NT GEMM (bf16 mma.sync) ------------------------
template <int COUT, int NTAPS>
__global__ __launch_bounds__(256) void conv_mma_kernel(const float* __restrict__ bias_v) {
    extern __shared__ unsigned char smem[];
    uint32_t sb = smem_u32(smem);
    const uint32_t AB0 = sb, BB0 = sb + 32768;

    int tid = threadIdx.x, lane = tid & 31, wid = tid >> 5;
    int wm = wid & 3, wn = wid >> 2;
    int b = blockIdx.z, m0 = blockIdx.y * 128, c0 = blockIdx.x * 128;

    const __nv_bfloat16* xTb = g_xT + (size_t)b * NPIX * CIN;
    const __nv_bfloat16* wb  = (NTAPS == 9) ? g_wvb : g_wkb;
    __nv_bfloat16* outp      = (NTAPS == 9) ? g_V : g_Kb;

    int arow[4], ach[4], ay[4], ax[4];
#pragma unroll
    for (int i = 0; i < 4; i++) {
        int idx = tid + i * 256;
        arow[i] = idx >> 3;
        ach[i]  = idx & 7;
        int p = m0 + arow[i];
        ay[i] = p / IMGW;
        ax[i] = p - ay[i] * IMGW;
    }

    const int NS = NTAPS * 4;
    auto load_stage = [&](int s, int buf) {
        int tap = (NTAPS == 9) ? (s >> 2) : 0;
        int kc  = s & 3;
        int dy = (NTAPS == 9) ? (tap / 3 - 1) : 0;
        int dx = (NTAPS == 9) ? (tap % 3 - 1) : 0;
        int off = dy * IMGW + dx;
        uint32_t ab = AB0 + buf * 16384, bb = BB0 + buf * 16384;
#pragma unroll
        for (int i = 0; i < 4; i++) {
            bool valid = (NTAPS == 1) ||
                         (((unsigned)(ay[i] + dy) < (unsigned)IMGW) &&
                          ((unsigned)(ax[i] + dx) < (unsigned)IMGW));
            int srow = m0 + arow[i] + (valid ? off : 0);
            cpa16(ab + arow[i] * 128 + ((ach[i] ^ (arow[i] & 7)) << 4),
                  xTb + (size_t)srow * CIN + kc * 64 + ach[i] * 8, valid ? 16 : 0);
            cpa16(bb + arow[i] * 128 + ((ach[i] ^ (arow[i] & 7)) << 4),
                  wb + (size_t)(tap * COUT + c0 + arow[i]) * CIN + kc * 64 + ach[i] * 8, 16);
        }
        CP_COMMIT();
    };

    float acc[2][8][4] = {};
    load_stage(0, 0);
    for (int s = 0; s < NS; s++) {
        if (s + 1 < NS) { load_stage(s + 1, (s + 1) & 1); CP_WAIT(1); }
        else            { CP_WAIT(0); }
        __syncthreads();
        uint32_t ab = AB0 + (s & 1) * 16384, bb = BB0 + (s & 1) * 16384;
#pragma unroll
        for (int kk = 0; kk < 4; kk++) {
            uint32_t a[2][4];
#pragma unroll
            for (int mt = 0; mt < 2; mt++) {
                int row = wm * 32 + mt * 16 + (lane & 15);
                int ch  = kk * 2 + (lane >> 4);
                ldsm4(a[mt], ab + row * 128 + ((ch ^ (row & 7)) << 4));
            }
            uint32_t bq[4][4];
#pragma unroll
            for (int np = 0; np < 4; np++) {
                int row = wn * 64 + np * 16 + (lane & 7) + ((lane >> 4) << 3);
                int ch  = kk * 2 + ((lane >> 3) & 1);
                ldsm4(bq[np], bb + row * 128 + ((ch ^ (row & 7)) << 4));
            }
#pragma unroll
            for (int mt = 0; mt < 2; mt++)
#pragma unroll
                for (int np = 0; np < 4; np++) {
                    mma_bf16(acc[mt][2 * np],     a[mt], bq[np][0], bq[np][1]);
                    mma_bf16(acc[mt][2 * np + 1], a[mt], bq[np][2], bq[np][3]);
                }
        }
        __syncthreads();
    }
#pragma unroll
    for (int mt = 0; mt < 2; mt++) {
        int r0 = m0 + wm * 32 + mt * 16 + (lane >> 2);
#pragma unroll
        for (int half = 0; half < 2; half++) {
            int rr = r0 + half * 8;
            __nv_bfloat16* op = outp + ((size_t)b * NPIX + rr) * COUT + c0;
#pragma unroll
            for (int nt = 0; nt < 8; nt++) {
                int col = wn * 64 + nt * 8 + (lane & 3) * 2;
                float b0 = (NTAPS == 9) ? bias_v[c0 + col]     : g_kbias[c0 + col];
                float b1 = (NTAPS == 9) ? bias_v[c0 + col + 1] : g_kbias[c0 + col + 1];
                __nv_bfloat162 h = __floats2bfloat162_rn(acc[mt][nt][half * 2] + b0,
                                                         acc[mt][nt][half * 2 + 1] + b1);
                *(uint32_t*)(op + col) = *(uint32_t*)&h;
            }
        }
    }
}

// ---------------- fused flash attention: ctx = softmax(K Kq^T) @ V ----------------
// QT=64 q rows per CTA, KT=128 k pixels per iter, C=256 full.
// smem: K0|K1 (2x32KB) | V0|V1 (2x64KB) | P (16KB) | stats (1KB)
__global__ __launch_bounds__(256) void flash_kernel() {
    extern __shared__ unsigned char smem[];
    const uint32_t sb = smem_u32(smem);
    const uint32_t KB = sb;                  // 2 x 32768
    const uint32_t VB = sb + 65536;          // 2 x 65536
    const uint32_t PB = sb + 65536 + 131072; // 16384
    float* pmax = (float*)(smem + 65536 + 131072 + 16384);        // [2][64]
    float* psum = (float*)(smem + 65536 + 131072 + 16384 + 512);  // [2][64]

    int tid = threadIdx.x, lane = tid & 31, wid = tid >> 5;
    int wm = wid & 3, wn = wid >> 2;   // wn doubles as wc in PV phase
    int b = blockIdx.y, q0 = blockIdx.x * QT;

    const __nv_bfloat16* Kb = g_Kb + (size_t)b * NPIX * CK;
    const __nv_bfloat16* Vb = g_V  + (size_t)b * NPIX * CV;

    // ---- stage Kq (64x128) into V-buf1 area, then load resident A fragments ----
#pragma unroll
    for (int i = 0; i < 4; i++) {
        int idx = tid + i * 256;           // 64 rows x 16 chunks
        int row = idx >> 4, ch = idx & 15;
        cpa16(VB + 65536 + row * 256 + ((ch ^ (row & 7)) << 4),
              Kb + (size_t)(q0 + row) * CK + ch * 8, 16);
    }
    CP_COMMIT();
    CP_WAIT(0);
    __syncthreads();
    uint32_t aq[8][4];
    {
        int row = wm * 16 + (lane & 15);
#pragma unroll
        for (int k16 = 0; k16 < 8; k16++) {
            int ch = k16 * 2 + (lane >> 4);
            ldsm4(aq[k16], VB + 65536 + row * 256 + ((ch ^ (row & 7)) << 4));
        }
    }

    // ---- K/V tile loader ----
    auto load_kv = [&](int it, int buf) {
        uint32_t kb = KB + buf * 32768, vb = VB + buf * 65536;
        int base = it * KT;
#pragma unroll
        for (int i = 0; i < 8; i++) {      // K: 128 rows x 16 chunks
            int idx = tid + i * 256;
            int row = idx >> 4, ch = idx & 15;
            cpa16(kb + row * 256 + ((ch ^ (row & 7)) << 4),
                  Kb + (size_t)(base + row) * CK + ch * 8, 16);
        }
#pragma unroll
        for (int i = 0; i < 16; i++) {     // V: 128 rows x 32 chunks
            int idx = tid + i * 256;
            int row = idx >> 5, ch = idx & 31;
            cpa16(vb + row * 512 + ((ch ^ (row & 7)) << 4),
                  Vb + (size_t)(base + row) * CV + ch * 8, 16);
        }
    };

    float m0 = -1e30f, m1 = -1e30f, l0 = 0.f, l1 = 0.f;
    float acc[8][2][4] = {};               // PV accum: 16 rows x 128 cols per warp

    int r0t = wm * 16 + (lane >> 2);       // this thread's rows within tile
    int r1t = r0t + 8;

    load_kv(0, 0);
    CP_COMMIT();

    for (int it = 0; it < NPIX / KT; it++) {
        int buf = it & 1;
        __syncthreads();                   // prev iter fully consumed
        if (it + 1 < NPIX / KT) load_kv(it + 1, buf ^ 1);
        CP_COMMIT();
        CP_WAIT(1);
        __syncthreads();                   // tiles for this iter visible to all

        uint32_t kb = KB + buf * 32768, vb = VB + buf * 65536;

        // ---- S = Kq @ Kk^T (this warp: 16 rows x 64 cols) ----
        float sacc[8][4] = {};
#pragma unroll
        for (int k16 = 0; k16 < 8; k16++) {
#pragma unroll
            for (int np = 0; np < 4; np++) {
                int row = wn * 64 + np * 16 + (lane & 7) + ((lane >> 4) << 3);
                int ch  = k16 * 2 + ((lane >> 3) & 1);
                uint32_t bq[4];
                ldsm4(bq, kb + row * 256 + ((ch ^ (row & 7)) << 4));
                mma_bf16(sacc[2 * np],     aq[k16], bq[0], bq[1]);
                mma_bf16(sacc[2 * np + 1], aq[k16], bq[2], bq[3]);
            }
        }

        // ---- online softmax: partial max ----
        float pm0 = -1e30f, pm1 = -1e30f;
#pragma unroll
        for (int f = 0; f < 8; f++) {
            pm0 = fmaxf(pm0, fmaxf(sacc[f][0], sacc[f][1]));
            pm1 = fmaxf(pm1, fmaxf(sacc[f][2], sacc[f][3]));
        }
        pm0 = fmaxf(pm0, __shfl_xor_sync(0xffffffff, pm0, 1));
        pm0 = fmaxf(pm0, __shfl_xor_sync(0xffffffff, pm0, 2));
        pm1 = fmaxf(pm1, __shfl_xor_sync(0xffffffff, pm1, 1));
        pm1 = fmaxf(pm1, __shfl_xor_sync(0xffffffff, pm1, 2));
        if ((lane & 3) == 0) {
            pmax[wn * 64 + r0t] = pm0;
            pmax[wn * 64 + r1t] = pm1;
        }
        __syncthreads();
        float mn0 = fmaxf(m0, fmaxf(pmax[r0t], pmax[64 + r0t]));
        float mn1 = fmaxf(m1, fmaxf(pmax[r1t], pmax[64 + r1t]));
        float sc0 = __expf(m0 - mn0), sc1 = __expf(m1 - mn1);
        m0 = mn0; m1 = mn1;

        // ---- exp, partial sums, write P to smem (bf16) ----
        float ps0 = 0.f, ps1 = 0.f;
#pragma unroll
        for (int np = 0; np < 4; np++) {
#pragma unroll
            for (int j = 0; j < 2; j++) {
                float* s = sacc[2 * np + j];
                float e0 = __expf(s[0] - mn0), e1 = __expf(s[1] - mn0);
                float e2 = __expf(s[2] - mn1), e3 = __expf(s[3] - mn1);
                ps0 += e0 + e1;
                ps1 += e2 + e3;
                int chunk = wn * 8 + np * 2 + j;
                int cb = (lane & 3) * 4;   // byte offset of col pair in chunk
                __nv_bfloat162 h0 = __floats2bfloat162_rn(e0, e1);
                __nv_bfloat162 h1 = __floats2bfloat162_rn(e2, e3);
                *(uint32_t*)(smem + (PB - sb) + r0t * 256 + ((chunk ^ (r0t & 7)) << 4) + cb) = *(uint32_t*)&h0;
                *(uint32_t*)(smem + (PB - sb) + r1t * 256 + ((chunk ^ (r1t & 7)) << 4) + cb) = *(uint32_t*)&h1;
            }
        }
        ps0 += __shfl_xor_sync(0xffffffff, ps0, 1);
        ps0 += __shfl_xor_sync(0xffffffff, ps0, 2);
        ps1 += __shfl_xor_sync(0xffffffff, ps1, 1);
        ps1 += __shfl_xor_sync(0xffffffff, ps1, 2);
        if ((lane & 3) == 0) {
            psum[wn * 64 + r0t] = ps0;
            psum[wn * 64 + r1t] = ps1;
        }
        __syncthreads();                   // stats + P visible
        l0 = l0 * sc0 + psum[r0t] + psum[64 + r0t];
        l1 = l1 * sc1 + psum[r1t] + psum[64 + r1t];

        // ---- rescale accumulators ----
#pragma unroll
        for (int np = 0; np < 8; np++)
#pragma unroll
            for (int j = 0; j < 2; j++) {
                acc[np][j][0] *= sc0; acc[np][j][1] *= sc0;
                acc[np][j][2] *= sc1; acc[np][j][3] *= sc1;
            }

        // ---- PV: acc += P @ V (this warp: 16 rows x 128 cols, cols wn*128..) ----
        {
            int prow = wm * 16 + (lane & 15);
#pragma unroll
            for (int k16 = 0; k16 < 8; k16++) {
                uint32_t ap[4];
                int ch = k16 * 2 + (lane >> 4);
                ldsm4(ap, PB + prow * 256 + ((ch ^ (prow & 7)) << 4));
                int krow = k16 * 16 + (lane & 7) + ((lane >> 3) & 1) * 8;
#pragma unroll
                for (int np = 0; np < 8; np++) {
                    int nch = wn * 16 + np * 2 + (lane >> 4);
                    uint32_t bq[4];
                    ldsm4t(bq, vb + krow * 512 + ((nch ^ (krow & 7)) << 4));
                    mma_bf16(acc[np][0], ap, bq[0], bq[1]);
                    mma_bf16(acc[np][1], ap, bq[2], bq[3]);
                }
            }
        }
    }

    // ---- epilogue: ctx = acc / l ----
    float inv0 = 1.0f / l0, inv1 = 1.0f / l1;
    float* cp0 = g_ctx + ((size_t)b * NPIX + q0 + r0t) * CV + wn * 128;
    float* cp1 = g_ctx + ((size_t)b * NPIX + q0 + r1t) * CV + wn * 128;
#pragma unroll
    for (int np = 0; np < 8; np++)
#pragma unroll
        for (int j = 0; j < 2; j++) {
            int col = np * 16 + j * 8 + (lane & 3) * 2;
            *(float2*)(cp0 + col) = make_float2(acc[np][j][0] * inv0, acc[np][j][1] * inv0);
            *(float2*)(cp1 + col) = make_float2(acc[np][j][2] * inv1, acc[np][j][3] * inv1);
        }
}

// ---------------- out[b][co][n] = ww @ ctx^T + bw + x (fp32 SIMT) -----------------
__global__ void gemm_out_kernel(const float* __restrict__ ww, const float* __restrict__ bw,
                                const float* __restrict__ x, float* __restrict__ out) {
    __shared__ float As[16][132];
    __shared__ float Bs[16][132];
    int b   = blockIdx.z;
    int co0 = blockIdx.y * 128;
    int n0  = blockIdx.x * 128;
    const float* ctxb = g_ctx + (size_t)b * NPIX * CV;

    int tid  = threadIdx.x;
    int f4   = tid & 3;
    int lrow = tid >> 2;
    int tx = tid & 15, ty = tid >> 4;

    float acc[8][8];
#pragma unroll
    for (int r = 0; r < 8; r++)
#pragma unroll
        for (int c = 0; c < 8; c++) acc[r][c] = 0.f;

    for (int k0 = 0; k0 < CV; k0 += 16) {
        __syncthreads();
#pragma unroll
        for (int l = 0; l < 2; l++) {
            int row = lrow + 64 * l;
            float4 va = *(const float4*)(ww + (size_t)(co0 + row) * CV + k0 + f4 * 4);
            As[f4 * 4 + 0][row] = va.x; As[f4 * 4 + 1][row] = va.y;
            As[f4 * 4 + 2][row] = va.z; As[f4 * 4 + 3][row] = va.w;
            float4 vb = *(const float4*)(ctxb + (size_t)(n0 + row) * CV + k0 + f4 * 4);
            Bs[f4 * 4 + 0][row] = vb.x; Bs[f4 * 4 + 1][row] = vb.y;
            Bs[f4 * 4 + 2][row] = vb.z; Bs[f4 * 4 + 3][row] = vb.w;
        }
        __syncthreads();
#pragma unroll
        for (int kk = 0; kk < 16; kk++) {
            float a[8], bv[8];
#pragma unroll
            for (int r = 0; r < 8; r++) a[r] = As[kk][ty * 8 + r];
#pragma unroll
            for (int c = 0; c < 8; c++) bv[c] = Bs[kk][tx * 8 + c];
#pragma unroll
            for (int r = 0; r < 8; r++)
#pragma unroll
                for (int c = 0; c < 8; c++) acc[r][c] += a[r] * bv[c];
        }
    }
#pragma unroll
    for (int r = 0; r < 8; r++) {
        int co = co0 + ty * 8 + r;
        float bwv = bw[co];
        size_t xbase = ((size_t)b * CIN + co) * NPIX + n0 + tx * 8;
        size_t obase = ((size_t)b * CV  + co) * NPIX + n0 + tx * 8;
        float4 x0 = *(const float4*)(x + xbase);
        float4 x1 = *(const float4*)(x + xbase + 4);
        float4 o0, o1;
        o0.x = acc[r][0] + bwv + x0.x; o0.y = acc[r][1] + bwv + x0.y;
        o0.z = acc[r][2] + bwv + x0.z; o0.w = acc[r][3] + bwv + x0.w;
        o1.x = acc[r][4] + bwv + x1.x; o1.y = acc[r][5] + bwv + x1.y;
        o1.z = acc[r][6] + bwv + x1.z; o1.w = acc[r][7] + bwv + x1.w;
        *(float4*)(out + obase)     = o0;
        *(float4*)(out + obase + 4) = o1;
    }
}

// ---------------- launch ----------------------------------------------------------
extern "C" void kernel_launch(void* const* d_in, const int* in_sizes, int n_in,
                              void* d_out, int out_size) {
    (void)in_sizes; (void)n_in; (void)out_size;
    const float* x     = (const float*)d_in[0];
    const float* wk    = (const float*)d_in[1];
    const float* bk    = (const float*)d_in[2];
    const float* gamma = (const float*)d_in[3];
    const float* beta  = (const float*)d_in[4];
    const float* rmean = (const float*)d_in[5];
    const float* rvar  = (const float*)d_in[6];
    const float* wv    = (const float*)d_in[7];
    const float* bv    = (const float*)d_in[8];
    const float* ww    = (const float*)d_in[9];
    const float* bw    = (const float*)d_in[10];
    float* out = (float*)d_out;

    const int MMA_SMEM = 65536;
    const int FLASH_SMEM = 65536 + 131072 + 16384 + 1024;  // 214016
    cudaFuncSetAttribute(conv_mma_kernel<CK, 1>, cudaFuncAttributeMaxDynamicSharedMemorySize, MMA_SMEM);
    cudaFuncSetAttribute(conv_mma_kernel<CV, 9>, cudaFuncAttributeMaxDynamicSharedMemorySize, MMA_SMEM);
    cudaFuncSetAttribute(flash_kernel, cudaFuncAttributeMaxDynamicSharedMemorySize, FLASH_SMEM);

    prep_kernel<<<256, 256>>>(wk, bk, gamma, beta, rmean, rvar, wv);
    transpose_x_kernel<<<dim3(NPIX / 32, CIN / 32, 2), 256>>>(x);
    conv_mma_kernel<CK, 1><<<dim3(1, NPIX / 128, 2), 256, MMA_SMEM>>>(bv);
    conv_mma_kernel<CV, 9><<<dim3(CV / 128, NPIX / 128, 2), 256, MMA_SMEM>>>(bv);
    flash_kernel<<<dim3(NPIX / QT, 2), 256, FLASH_SMEM>>>();
    gemm_out_kernel<<<dim3(NPIX / 128, CV / 128, 2), 256>>>(ww, bw, x, out);
}

// round 5
// speedup vs baseline: 1.2944x; 1.2944x over previous
#include <cuda_runtime.h>
#include <cuda_bf16.h>
#include <stdint.h>

#define NPIX 6400
#define IMGW 80
#define CIN 256
#define CK 128
#define CV 256
#define QT 64
#define KT 128
#define NSPLIT 2
#define KCH (NPIX / NSPLIT)
#define NIT (KCH / KT)

// ---------------- scratch ----------------
__device__ __nv_bfloat16 g_xT[(size_t)2 * NPIX * CIN];  // [b][n][c]
__device__ __nv_bfloat16 g_Kb[(size_t)2 * NPIX * CK];   // [b][n][c]
__device__ __nv_bfloat16 g_V[(size_t)2 * NPIX * CV];    // [b][n][c]
__device__ float g_part[(size_t)2 * NSPLIT * NPIX * CV];// unnormalized PV partials
__device__ float g_l[2 * NSPLIT * NPIX];                // row sums per split
__device__ float g_ctx[(size_t)2 * NPIX * CV];          // [b][n][c]
__device__ float g_kbias[CK];
__device__ __nv_bfloat16 g_wkb[CK * CIN];
__device__ __nv_bfloat16 g_wvb[9 * CV * CIN];

// ---------------- PTX helpers ----------------
__device__ __forceinline__ uint32_t smem_u32(const void* p) {
    uint32_t a;
    asm("{ .reg .u64 t; cvta.to.shared.u64 t, %1; cvt.u32.u64 %0, t; }" : "=r"(a) : "l"(p));
    return a;
}
__device__ __forceinline__ void ldsm4(uint32_t* r, uint32_t addr) {
    asm volatile("ldmatrix.sync.aligned.m8n8.x4.shared.b16 {%0,%1,%2,%3}, [%4];"
                 : "=r"(r[0]), "=r"(r[1]), "=r"(r[2]), "=r"(r[3]) : "r"(addr));
}
__device__ __forceinline__ void ldsm4t(uint32_t* r, uint32_t addr) {
    asm volatile("ldmatrix.sync.aligned.m8n8.x4.trans.shared.b16 {%0,%1,%2,%3}, [%4];"
                 : "=r"(r[0]), "=r"(r[1]), "=r"(r[2]), "=r"(r[3]) : "r"(addr));
}
__device__ __forceinline__ void mma_bf16(float* c, const uint32_t* a, uint32_t b0, uint32_t b1) {
    asm volatile("mma.sync.aligned.m16n8k16.row.col.f32.bf16.bf16.f32 "
                 "{%0,%1,%2,%3}, {%4,%5,%6,%7}, {%8,%9}, {%0,%1,%2,%3};"
                 : "+f"(c[0]), "+f"(c[1]), "+f"(c[2]), "+f"(c[3])
                 : "r"(a[0]), "r"(a[1]), "r"(a[2]), "r"(a[3]), "r"(b0), "r"(b1));
}
__device__ __forceinline__ void cpa16(uint32_t dst, const void* src, int sz) {
    asm volatile("cp.async.cg.shared.global [%0], [%1], 16, %2;"
                 :: "r"(dst), "l"(src), "r"(sz));
}
#define CP_COMMIT() asm volatile("cp.async.commit_group;" ::: "memory")
#define CP_WAIT(n)  asm volatile("cp.async.wait_group %0;" :: "n"(n) : "memory")

// ---------------- weight prep ----------------
__global__ void prep_kernel(const float* __restrict__ wk, const float* __restrict__ bk,
                            const float* __restrict__ gamma, const float* __restrict__ beta,
                            const float* __restrict__ rmean, const float* __restrict__ rvar,
                            const float* __restrict__ wv) {
    int tid = blockIdx.x * blockDim.x + threadIdx.x;
    int nth = gridDim.x * blockDim.x;
    if (tid < CK) {
        float inv = gamma[tid] * rsqrtf(rvar[tid] + 1e-5f);
        g_kbias[tid] = bk[tid] * inv + beta[tid] - rmean[tid] * inv;
    }
    for (int idx = tid; idx < CK * CIN; idx += nth) {
        int c = idx / CIN;
        float inv = gamma[c] * rsqrtf(rvar[c] + 1e-5f);
        g_wkb[idx] = __float2bfloat16(wk[idx] * inv);
    }
    for (int idx = tid; idx < 9 * CV * CIN; idx += nth) {
        int t = idx / (CV * CIN);
        int rem = idx - t * CV * CIN;
        int o = rem / CIN;
        int i = rem - o * CIN;
        g_wvb[idx] = __float2bfloat16(wv[(o * CIN + i) * 9 + t]);
    }
}

// ---------------- x transpose: [b][c][n] fp32 -> [b][n][c] bf16 -------------------
__global__ void transpose_x_kernel(const float* __restrict__ x) {
    __shared__ float t[32][33];
    int b = blockIdx.z, n0 = blockIdx.x * 32, c0 = blockIdx.y * 32;
    int tid = threadIdx.x, nl = tid & 31, cg = tid >> 5;
#pragma unroll
    for (int i = 0; i < 4; i++) {
        int c = cg + i * 8;
        t[c][nl] = x[((size_t)b * CIN + c0 + c) * NPIX + n0 + nl];
    }
    __syncthreads();
    __nv_bfloat162 h0 = __floats2bfloat162_rn(t[cg * 4 + 0][nl], t[cg * 4 + 1][nl]);
    __nv_bfloat162 h1 = __floats2bfloat162_rn(t[cg * 4 + 2][nl], t[cg * 4 + 3][nl]);
    uint2 v;
    v.x = *(uint32_t*)&h0; v.y = *(uint32_t*)&h1;
    *(uint2*)(g_xT + ((size_t)b * NPIX + n0 + nl) * CIN + c0 + cg * 4) = v;
}

// ---------------- conv as implicit NT GEMM (bf16 mma.sync) ------------------------
template <int COUT, int NTAPS>
__global__ __launch_bounds__(256) void conv_mma_kernel(const float* __restrict__ bias_v) {
    extern __shared__ unsigned char smem[];
    uint32_t sb = smem_u32(smem);
    const uint32_t AB0 = sb, BB0 = sb + 32768;

    int tid = threadIdx.x, lane = tid & 31, wid = tid >> 5;
    int wm = wid & 3, wn = wid >> 2;
    int b = blockIdx.z, m0 = blockIdx.y * 128, c0 = blockIdx.x * 128;

    const __nv_bfloat16* xTb = g_xT + (size_t)b * NPIX * CIN;
    const __nv_bfloat16* wb  = (NTAPS == 9) ? g_wvb : g_wkb;
    __nv_bfloat16* outp      = (NTAPS == 9) ? g_V : g_Kb;

    int arow[4], ach[4], ay[4], ax[4];
#pragma unroll
    for (int i = 0; i < 4; i++) {
        int idx = tid + i * 256;
        arow[i] = idx >> 3;
        ach[i]  = idx & 7;
        int p = m0 + arow[i];
        ay[i] = p / IMGW;
        ax[i] = p - ay[i] * IMGW;
    }

    const int NS = NTAPS * 4;
    auto load_stage = [&](int s, int buf) {
        int tap = (NTAPS == 9) ? (s >> 2) : 0;
        int kc  = s & 3;
        int dy = (NTAPS == 9) ? (tap / 3 - 1) : 0;
        int dx = (NTAPS == 9) ? (tap % 3 - 1) : 0;
        int off = dy * IMGW + dx;
        uint32_t ab = AB0 + buf * 16384, bb = BB0 + buf * 16384;
#pragma unroll
        for (int i = 0; i < 4; i++) {
            bool valid = (NTAPS == 1) ||
                         (((unsigned)(ay[i] + dy) < (unsigned)IMGW) &&
                          ((unsigned)(ax[i] + dx) < (unsigned)IMGW));
            int srow = m0 + arow[i] + (valid ? off : 0);
            cpa16(ab + arow[i] * 128 + ((ach[i] ^ (arow[i] & 7)) << 4),
                  xTb + (size_t)srow * CIN + kc * 64 + ach[i] * 8, valid ? 16 : 0);
            cpa16(bb + arow[i] * 128 + ((ach[i] ^ (arow[i] & 7)) << 4),
                  wb + (size_t)(tap * COUT + c0 + arow[i]) * CIN + kc * 64 + ach[i] * 8, 16);
        }
        CP_COMMIT();
    };

    float acc[2][8][4] = {};
    load_stage(0, 0);
    for (int s = 0; s < NS; s++) {
        if (s + 1 < NS) { load_stage(s + 1, (s + 1) & 1); CP_WAIT(1); }
        else            { CP_WAIT(0); }
        __syncthreads();
        uint32_t ab = AB0 + (s & 1) * 16384, bb = BB0 + (s & 1) * 16384;
#pragma unroll
        for (int kk = 0; kk < 4; kk++) {
            uint32_t a[2][4];
#pragma unroll
            for (int mt = 0; mt < 2; mt++) {
                int row = wm * 32 + mt * 16 + (lane & 15);
                int ch  = kk * 2 + (lane >> 4);
                ldsm4(a[mt], ab + row * 128 + ((ch ^ (row & 7)) << 4));
            }
            uint32_t bq[4][4];
#pragma unroll
            for (int np = 0; np < 4; np++) {
                int row = wn * 64 + np * 16 + (lane & 7) + ((lane >> 4) << 3);
                int ch  = kk * 2 + ((lane >> 3) & 1);
                ldsm4(bq[np], bb + row * 128 + ((ch ^ (row & 7)) << 4));
            }
#pragma unroll
            for (int mt = 0; mt < 2; mt++)
#pragma unroll
                for (int np = 0; np < 4; np++) {
                    mma_bf16(acc[mt][2 * np],     a[mt], bq[np][0], bq[np][1]);
                    mma_bf16(acc[mt][2 * np + 1], a[mt], bq[np][2], bq[np][3]);
                }
        }
        __syncthreads();
    }
#pragma unroll
    for (int mt = 0; mt < 2; mt++) {
        int r0 = m0 + wm * 32 + mt * 16 + (lane >> 2);
#pragma unroll
        for (int half = 0; half < 2; half++) {
            int rr = r0 + half * 8;
            __nv_bfloat16* op = outp + ((size_t)b * NPIX + rr) * COUT + c0;
#pragma unroll
            for (int nt = 0; nt < 8; nt++) {
                int col = wn * 64 + nt * 8 + (lane & 3) * 2;
                float b0 = (NTAPS == 9) ? bias_v[c0 + col]     : g_kbias[c0 + col];
                float b1 = (NTAPS == 9) ? bias_v[c0 + col + 1] : g_kbias[c0 + col + 1];
                __nv_bfloat162 h = __floats2bfloat162_rn(acc[mt][nt][half * 2] + b0,
                                                         acc[mt][nt][half * 2 + 1] + b1);
                *(uint32_t*)(op + col) = *(uint32_t*)&h;
            }
        }
    }
}

// ---------------- fused flash attention (split-K, no max-shift) -------------------
// Job = (q-tile 64 rows, k-range 3200). exp(S) directly (logits bounded ~|25|).
// Partial o (unnormalized) + row-sum l written per split; combined later.
__global__ __launch_bounds__(256) void flash_kernel() {
    extern __shared__ unsigned char smem[];
    const uint32_t sb = smem_u32(smem);
    const uint32_t KB = sb;                  // 2 x 32768
    const uint32_t VB = sb + 65536;          // 2 x 65536
    const uint32_t PB = sb + 65536 + 131072; // 16384
    float* psum = (float*)(smem + 65536 + 131072 + 16384);  // [2][64]

    int tid = threadIdx.x, lane = tid & 31, wid = tid >> 5;
    int wm = wid & 3, wn = wid >> 2;   // S phase: 4m x 2n
    int pm = wid & 1, pc = wid >> 1;   // PV phase: 2m x 4c
    int b = blockIdx.z, q0 = blockIdx.x * QT, split = blockIdx.y;
    int kbase = split * KCH;

    const __nv_bfloat16* Kb = g_Kb + (size_t)b * NPIX * CK;
    const __nv_bfloat16* Vb = g_V  + (size_t)b * NPIX * CV;

    // ---- stage Kq (64x128) into V-buf1 area; load resident A fragments ----
#pragma unroll
    for (int i = 0; i < 4; i++) {
        int idx = tid + i * 256;
        int row = idx >> 4, ch = idx & 15;
        cpa16(VB + 65536 + row * 256 + ((ch ^ (row & 7)) << 4),
              Kb + (size_t)(q0 + row) * CK + ch * 8, 16);
    }
    CP_COMMIT();
    CP_WAIT(0);
    __syncthreads();
    uint32_t aq[8][4];
    {
        int row = wm * 16 + (lane & 15);
#pragma unroll
        for (int k16 = 0; k16 < 8; k16++) {
            int ch = k16 * 2 + (lane >> 4);
            ldsm4(aq[k16], VB + 65536 + row * 256 + ((ch ^ (row & 7)) << 4));
        }
    }

    auto load_kv = [&](int it, int buf) {
        uint32_t kb = KB + buf * 32768, vb = VB + buf * 65536;
        int base = kbase + it * KT;
#pragma unroll
        for (int i = 0; i < 8; i++) {
            int idx = tid + i * 256;
            int row = idx >> 4, ch = idx & 15;
            cpa16(kb + row * 256 + ((ch ^ (row & 7)) << 4),
                  Kb + (size_t)(base + row) * CK + ch * 8, 16);
        }
#pragma unroll
        for (int i = 0; i < 16; i++) {
            int idx = tid + i * 256;
            int row = idx >> 5, ch = idx & 31;
            cpa16(vb + row * 512 + ((ch ^ (row & 7)) << 4),
                  Vb + (size_t)(base + row) * CV + ch * 8, 16);
        }
    };

    float acc[2][8][4] = {};           // PV accum: 32 rows x 64 cols per warp
    float ps0 = 0.f, ps1 = 0.f;        // running row sums (softmax-layout rows)
    int r0t = wm * 16 + (lane >> 2);
    int r1t = r0t + 8;

    load_kv(0, 0);
    CP_COMMIT();

    for (int it = 0; it < NIT; it++) {
        int buf = it & 1;
        __syncthreads();               // prev P + prev tiles consumed
        if (it + 1 < NIT) load_kv(it + 1, buf ^ 1);
        CP_COMMIT();
        CP_WAIT(1);
        __syncthreads();               // this iter's K/V visible

        uint32_t kb = KB + buf * 32768, vb = VB + buf * 65536;

        // ---- S = Kq @ Kk^T (warp: 16 rows x 64 cols) ----
        float sacc[8][4] = {};
#pragma unroll
        for (int k16 = 0; k16 < 8; k16++) {
#pragma unroll
            for (int np = 0; np < 4; np++) {
                int row = wn * 64 + np * 16 + (lane & 7) + ((lane >> 4) << 3);
                int ch  = k16 * 2 + ((lane >> 3) & 1);
                uint32_t bq[4];
                ldsm4(bq, kb + row * 256 + ((ch ^ (row & 7)) << 4));
                mma_bf16(sacc[2 * np],     aq[k16], bq[0], bq[1]);
                mma_bf16(sacc[2 * np + 1], aq[k16], bq[2], bq[3]);
            }
        }

        // ---- P = exp(S) (no shift); accumulate row sums; write P bf16 ----
#pragma unroll
        for (int np = 0; np < 4; np++) {
#pragma unroll
            for (int j = 0; j < 2; j++) {
                float* s = sacc[2 * np + j];
                float e0 = __expf(s[0]), e1 = __expf(s[1]);
                float e2 = __expf(s[2]), e3 = __expf(s[3]);
                ps0 += e0 + e1;
                ps1 += e2 + e3;
                int chunk = wn * 8 + np * 2 + j;
                int cb = (lane & 3) * 4;
                __nv_bfloat162 h0 = __floats2bfloat162_rn(e0, e1);
                __nv_bfloat162 h1 = __floats2bfloat162_rn(e2, e3);
                *(uint32_t*)(smem + (PB - sb) + r0t * 256 + ((chunk ^ (r0t & 7)) << 4) + cb) = *(uint32_t*)&h0;
                *(uint32_t*)(smem + (PB - sb) + r1t * 256 + ((chunk ^ (r1t & 7)) << 4) + cb) = *(uint32_t*)&h1;
            }
        }
        __syncthreads();               // P visible

        // ---- PV: acc += P @ V (warp: 32 rows x 64 cols) ----
        {
            int prowb = pm * 32 + (lane & 15);
#pragma unroll
            for (int k16 = 0; k16 < 8; k16++) {
                uint32_t ap[2][4];
                int ch = k16 * 2 + (lane >> 4);
                ldsm4(ap[0], PB + prowb * 256 + ((ch ^ (prowb & 7)) << 4));
                ldsm4(ap[1], PB + (prowb + 16) * 256 + ((ch ^ ((prowb + 16) & 7)) << 4));
                int krow = k16 * 16 + (lane & 7) + ((lane >> 3) & 1) * 8;
#pragma unroll
                for (int np = 0; np < 4; np++) {
                    int nch = pc * 8 + np * 2 + (lane >> 4);
                    uint32_t bq[4];
                    ldsm4t(bq, vb + krow * 512 + ((nch ^ (krow & 7)) << 4));
                    mma_bf16(acc[0][2 * np],     ap[0], bq[0], bq[1]);
                    mma_bf16(acc[0][2 * np + 1], ap[0], bq[2], bq[3]);
                    mma_bf16(acc[1][2 * np],     ap[1], bq[0], bq[1]);
                    mma_bf16(acc[1][2 * np + 1], ap[1], bq[2], bq[3]);
                }
            }
        }
    }

    // ---- epilogue: reduce l, write partials ----
    ps0 += __shfl_xor_sync(0xffffffff, ps0, 1);
    ps0 += __shfl_xor_sync(0xffffffff, ps0, 2);
    ps1 += __shfl_xor_sync(0xffffffff, ps1, 1);
    ps1 += __shfl_xor_sync(0xffffffff, ps1, 2);
    if ((lane & 3) == 0) {
        psum[wn * 64 + r0t] = ps0;
        psum[wn * 64 + r1t] = ps1;
    }
    __syncthreads();
    if (tid < 64)
        g_l[(b * NSPLIT + split) * NPIX + q0 + tid] = psum[tid] + psum[64 + tid];

    float* op = g_part + ((size_t)(b * NSPLIT + split) * NPIX + q0) * CV;
#pragma unroll
    for (int mt = 0; mt < 2; mt++) {
        int r = pm * 32 + mt * 16 + (lane >> 2);
#pragma unroll
        for (int n8 = 0; n8 < 8; n8++) {
            int col = pc * 64 + n8 * 8 + (lane & 3) * 2;
            *(float2*)(op + (size_t)r * CV + col)       = make_float2(acc[mt][n8][0], acc[mt][n8][1]);
            *(float2*)(op + (size_t)(r + 8) * CV + col) = make_float2(acc[mt][n8][2], acc[mt][n8][3]);
        }
    }
}

// ---------------- combine: ctx = (o0 + o1) / (l0 + l1) ---------------------------
__global__ void combine_kernel() {
    int idx = blockIdx.x * 4 + (threadIdx.x >> 6);   // row id over 2*NPIX
    int b = idx / NPIX, n = idx - b * NPIX;
    int c = (threadIdx.x & 63) * 4;
    float l0 = g_l[(b * NSPLIT + 0) * NPIX + n];
    float l1 = g_l[(b * NSPLIT + 1) * NPIX + n];
    float inv = 1.0f / (l0 + l1);
    const float* p0 = g_part + ((size_t)(b * NSPLIT + 0) * NPIX + n) * CV + c;
    const float* p1 = g_part + ((size_t)(b * NSPLIT + 1) * NPIX + n) * CV + c;
    float4 a = *(const float4*)p0;
    float4 bb = *(const float4*)p1;
    float4 o;
    o.x = (a.x + bb.x) * inv; o.y = (a.y + bb.y) * inv;
    o.z = (a.z + bb.z) * inv; o.w = (a.w + bb.w) * inv;
    *(float4*)(g_ctx + ((size_t)b * NPIX + n) * CV + c) = o;
}

// ---------------- out[b][co][n] = ww @ ctx^T + bw + x (fp32 SIMT) -----------------
__global__ void gemm_out_kernel(const float* __restrict__ ww, const float* __restrict__ bw,
                                const float* __restrict__ x, float* __restrict__ out) {
    __shared__ float As[16][132];
    __shared__ float Bs[16][132];
    int b   = blockIdx.z;
    int co0 = blockIdx.y * 128;
    int n0  = blockIdx.x * 128;
    const float* ctxb = g_ctx + (size_t)b * NPIX * CV;

    int tid  = threadIdx.x;
    int f4   = tid & 3;
    int lrow = tid >> 2;
    int tx = tid & 15, ty = tid >> 4;

    float acc[8][8];
#pragma unroll
    for (int r = 0; r < 8; r++)
#pragma unroll
        for (int c = 0; c < 8; c++) acc[r][c] = 0.f;

    for (int k0 = 0; k0 < CV; k0 += 16) {
        __syncthreads();
#pragma unroll
        for (int l = 0; l < 2; l++) {
            int row = lrow + 64 * l;
            float4 va = *(const float4*)(ww + (size_t)(co0 + row) * CV + k0 + f4 * 4);
            As[f4 * 4 + 0][row] = va.x; As[f4 * 4 + 1][row] = va.y;
            As[f4 * 4 + 2][row] = va.z; As[f4 * 4 + 3][row] = va.w;
            float4 vb = *(const float4*)(ctxb + (size_t)(n0 + row) * CV + k0 + f4 * 4);
            Bs[f4 * 4 + 0][row] = vb.x; Bs[f4 * 4 + 1][row] = vb.y;
            Bs[f4 * 4 + 2][row] = vb.z; Bs[f4 * 4 + 3][row] = vb.w;
        }
        __syncthreads();
#pragma unroll
        for (int kk = 0; kk < 16; kk++) {
            float a[8], bv[8];
#pragma unroll
            for (int r = 0; r < 8; r++) a[r] = As[kk][ty * 8 + r];
#pragma unroll
            for (int c = 0; c < 8; c++) bv[c] = Bs[kk][tx * 8 + c];
#pragma unroll
            for (int r = 0; r < 8; r++)
#pragma unroll
                for (int c = 0; c < 8; c++) acc[r][c] += a[r] * bv[c];
        }
    }
#pragma unroll
    for (int r = 0; r < 8; r++) {
        int co = co0 + ty * 8 + r;
        float bwv = bw[co];
        size_t xbase = ((size_t)b * CIN + co) * NPIX + n0 + tx * 8;
        size_t obase = ((size_t)b * CV  + co) * NPIX + n0 + tx * 8;
        float4 x0 = *(const float4*)(x + xbase);
        float4 x1 = *(const float4*)(x + xbase + 4);
        float4 o0, o1;
        o0.x = acc[r][0] + bwv + x0.x; o0.y = acc[r][1] + bwv + x0.y;
        o0.z = acc[r][2] + bwv + x0.z; o0.w = acc[r][3] + bwv + x0.w;
        o1.x = acc[r][4] + bwv + x1.x; o1.y = acc[r][5] + bwv + x1.y;
        o1.z = acc[r][6] + bwv + x1.z; o1.w = acc[r][7] + bwv + x1.w;
        *(float4*)(out + obase)     = o0;
        *(float4*)(out + obase + 4) = o1;
    }
}

// ---------------- launch ----------------------------------------------------------
extern "C" void kernel_launch(void* const* d_in, const int* in_sizes, int n_in,
                              void* d_out, int out_size) {
    (void)in_sizes; (void)n_in; (void)out_size;
    const float* x     = (const float*)d_in[0];
    const float* wk    = (const float*)d_in[1];
    const float* bk    = (const float*)d_in[2];
    const float* gamma = (const float*)d_in[3];
    const float* beta  = (const float*)d_in[4];
    const float* rmean = (const float*)d_in[5];
    const float* rvar  = (const float*)d_in[6];
    const float* wv    = (const float*)d_in[7];
    const float* bv    = (const float*)d_in[8];
    const float* ww    = (const float*)d_in[9];
    const float* bw    = (const float*)d_in[10];
    float* out = (float*)d_out;

    const int MMA_SMEM = 65536;
    const int FLASH_SMEM = 65536 + 131072 + 16384 + 512;  // 213504
    cudaFuncSetAttribute(conv_mma_kernel<CK, 1>, cudaFuncAttributeMaxDynamicSharedMemorySize, MMA_SMEM);
    cudaFuncSetAttribute(conv_mma_kernel<CV, 9>, cudaFuncAttributeMaxDynamicSharedMemorySize, MMA_SMEM);
    cudaFuncSetAttribute(flash_kernel, cudaFuncAttributeMaxDynamicSharedMemorySize, FLASH_SMEM);

    prep_kernel<<<256, 256>>>(wk, bk, gamma, beta, rmean, rvar, wv);
    transpose_x_kernel<<<dim3(NPIX / 32, CIN / 32, 2), 256>>>(x);
    conv_mma_kernel<CK, 1><<<dim3(1, NPIX / 128, 2), 256, MMA_SMEM>>>(bv);
    conv_mma_kernel<CV, 9><<<dim3(CV / 128, NPIX / 128, 2), 256, MMA_SMEM>>>(bv);
    flash_kernel<<<dim3(NPIX / QT, NSPLIT, 2), 256, FLASH_SMEM>>>();
    combine_kernel<<<2 * NPIX / 4, 256>>>();
    gemm_out_kernel<<<dim3(NPIX / 128, CV / 128, 2), 256>>>(ww, bw, x, out);
}

// round 6
// speedup vs baseline: 1.4939x; 1.1541x over previous
#include <cuda_runtime.h>
#include <cuda_bf16.h>
#include <cuda_fp16.h>
#include <stdint.h>

#define NPIX 6400
#define IMGW 80
#define CIN 256
#define CK 128
#define CV 256
#define QT 64
#define KT 128
#define NSPLIT 2
#define KCH (NPIX / NSPLIT)
#define NIT (KCH / KT)

// ---------------- scratch ----------------
__device__ __half g_xT[(size_t)2 * NPIX * CIN];         // [b][n][c] fp16
__device__ __half g_Kh[(size_t)2 * NPIX * CK];          // [b][n][c] fp16
__device__ __nv_bfloat16 g_V[(size_t)2 * NPIX * CV];    // [b][n][c] bf16 (PV operand)
__device__ float g_part[(size_t)2 * NSPLIT * NPIX * CV];
__device__ float g_l[2 * NSPLIT * NPIX];
__device__ __half g_ctxh[(size_t)2 * NPIX * CV];        // [b][n][c] fp16
__device__ float g_kbias[CK];
__device__ __half g_wkh[CK * CIN];
__device__ __half g_wvh[9 * CV * CIN];
__device__ __half g_wwh[CV * CV];

// ---------------- PTX helpers ----------------
__device__ __forceinline__ uint32_t smem_u32(const void* p) {
    uint32_t a;
    asm("{ .reg .u64 t; cvta.to.shared.u64 t, %1; cvt.u32.u64 %0, t; }" : "=r"(a) : "l"(p));
    return a;
}
__device__ __forceinline__ void ldsm4(uint32_t* r, uint32_t addr) {
    asm volatile("ldmatrix.sync.aligned.m8n8.x4.shared.b16 {%0,%1,%2,%3}, [%4];"
                 : "=r"(r[0]), "=r"(r[1]), "=r"(r[2]), "=r"(r[3]) : "r"(addr));
}
__device__ __forceinline__ void ldsm4t(uint32_t* r, uint32_t addr) {
    asm volatile("ldmatrix.sync.aligned.m8n8.x4.trans.shared.b16 {%0,%1,%2,%3}, [%4];"
                 : "=r"(r[0]), "=r"(r[1]), "=r"(r[2]), "=r"(r[3]) : "r"(addr));
}
__device__ __forceinline__ void mma_bf16(float* c, const uint32_t* a, uint32_t b0, uint32_t b1) {
    asm volatile("mma.sync.aligned.m16n8k16.row.col.f32.bf16.bf16.f32 "
                 "{%0,%1,%2,%3}, {%4,%5,%6,%7}, {%8,%9}, {%0,%1,%2,%3};"
                 : "+f"(c[0]), "+f"(c[1]), "+f"(c[2]), "+f"(c[3])
                 : "r"(a[0]), "r"(a[1]), "r"(a[2]), "r"(a[3]), "r"(b0), "r"(b1));
}
__device__ __forceinline__ void mma_f16(float* c, const uint32_t* a, uint32_t b0, uint32_t b1) {
    asm volatile("mma.sync.aligned.m16n8k16.row.col.f32.f16.f16.f32 "
                 "{%0,%1,%2,%3}, {%4,%5,%6,%7}, {%8,%9}, {%0,%1,%2,%3};"
                 : "+f"(c[0]), "+f"(c[1]), "+f"(c[2]), "+f"(c[3])
                 : "r"(a[0]), "r"(a[1]), "r"(a[2]), "r"(a[3]), "r"(b0), "r"(b1));
}
__device__ __forceinline__ void cpa16(uint32_t dst, const void* src, int sz) {
    asm volatile("cp.async.cg.shared.global [%0], [%1], 16, %2;"
                 :: "r"(dst), "l"(src), "r"(sz));
}
#define CP_COMMIT() asm volatile("cp.async.commit_group;" ::: "memory")
#define CP_WAIT(n)  asm volatile("cp.async.wait_group %0;" :: "n"(n) : "memory")

// ---------------- weight prep (fp16) ----------------
__global__ void prep_kernel(const float* __restrict__ wk, const float* __restrict__ bk,
                            const float* __restrict__ gamma, const float* __restrict__ beta,
                            const float* __restrict__ rmean, const float* __restrict__ rvar,
                            const float* __restrict__ wv, const float* __restrict__ ww) {
    int tid = blockIdx.x * blockDim.x + threadIdx.x;
    int nth = gridDim.x * blockDim.x;
    if (tid < CK) {
        float inv = gamma[tid] * rsqrtf(rvar[tid] + 1e-5f);
        g_kbias[tid] = bk[tid] * inv + beta[tid] - rmean[tid] * inv;
    }
    for (int idx = tid; idx < CK * CIN; idx += nth) {
        int c = idx / CIN;
        float inv = gamma[c] * rsqrtf(rvar[c] + 1e-5f);
        g_wkh[idx] = __float2half(wk[idx] * inv);
    }
    for (int idx = tid; idx < CV * CV; idx += nth)
        g_wwh[idx] = __float2half(ww[idx]);
    for (int idx = tid; idx < 9 * CV * CIN; idx += nth) {
        int t = idx / (CV * CIN);
        int rem = idx - t * CV * CIN;
        int o = rem / CIN;
        int i = rem - o * CIN;
        g_wvh[idx] = __float2half(wv[(o * CIN + i) * 9 + t]);
    }
}

// ---------------- x transpose: [b][c][n] fp32 -> [b][n][c] fp16 -------------------
__global__ void transpose_x_kernel(const float* __restrict__ x) {
    __shared__ float t[32][33];
    int b = blockIdx.z, n0 = blockIdx.x * 32, c0 = blockIdx.y * 32;
    int tid = threadIdx.x, nl = tid & 31, cg = tid >> 5;
#pragma unroll
    for (int i = 0; i < 4; i++) {
        int c = cg + i * 8;
        t[c][nl] = x[((size_t)b * CIN + c0 + c) * NPIX + n0 + nl];
    }
    __syncthreads();
    __half2 h0 = __floats2half2_rn(t[cg * 4 + 0][nl], t[cg * 4 + 1][nl]);
    __half2 h1 = __floats2half2_rn(t[cg * 4 + 2][nl], t[cg * 4 + 3][nl]);
    uint2 v;
    v.x = *(uint32_t*)&h0; v.y = *(uint32_t*)&h1;
    *(uint2*)(g_xT + ((size_t)b * NPIX + n0 + nl) * CIN + c0 + cg * 4) = v;
}

// ---------------- conv as implicit NT GEMM (fp16 mma, BK=128) ---------------------
// Stage = (tap, kc): 128 pixels x 128 ch A-tile + 128 couts x 128 ch B-tile.
template <int COUT, int NTAPS>
__global__ __launch_bounds__(256) void conv_mma_kernel(const float* __restrict__ bias_v) {
    extern __shared__ unsigned char smem[];
    uint32_t sb = smem_u32(smem);
    const uint32_t AB0 = sb, BB0 = sb + 65536;   // 2x32KB each

    int tid = threadIdx.x, lane = tid & 31, wid = tid >> 5;
    int wm = wid & 3, wn = wid >> 2;
    int b = blockIdx.z, m0 = blockIdx.y * 128, c0 = blockIdx.x * 128;

    const __half* xTb = g_xT + (size_t)b * NPIX * CIN;
    const __half* wb  = (NTAPS == 9) ? g_wvh : g_wkh;

    int lch = tid & 15;                  // chunk index (fixed per thread)
    int ay[8], ax[8];
#pragma unroll
    for (int i = 0; i < 8; i++) {
        int row = (tid >> 4) + i * 16;
        int p = m0 + row;
        ay[i] = p / IMGW;
        ax[i] = p - ay[i] * IMGW;
    }

    const int NS = NTAPS * 2;
    auto load_stage = [&](int s, int buf) {
        int tap = (NTAPS == 9) ? (s >> 1) : 0;
        int kc  = s & 1;
        int dy = (NTAPS == 9) ? (tap / 3 - 1) : 0;
        int dx = (NTAPS == 9) ? (tap % 3 - 1) : 0;
        int off = dy * IMGW + dx;
        uint32_t ab = AB0 + buf * 32768, bb = BB0 + buf * 32768;
#pragma unroll
        for (int i = 0; i < 8; i++) {
            int row = (tid >> 4) + i * 16;
            bool valid = (NTAPS == 1) ||
                         (((unsigned)(ay[i] + dy) < (unsigned)IMGW) &&
                          ((unsigned)(ax[i] + dx) < (unsigned)IMGW));
            int srow = m0 + row + (valid ? off : 0);
            uint32_t soff = row * 256 + ((lch ^ (row & 7)) << 4);
            cpa16(ab + soff, xTb + (size_t)srow * CIN + kc * 128 + lch * 8, valid ? 16 : 0);
            cpa16(bb + soff, wb + (size_t)(tap * COUT + c0 + row) * CIN + kc * 128 + lch * 8, 16);
        }
        CP_COMMIT();
    };

    float acc[2][8][4] = {};
    load_stage(0, 0);
    for (int s = 0; s < NS; s++) {
        if (s + 1 < NS) { load_stage(s + 1, (s + 1) & 1); CP_WAIT(1); }
        else            { CP_WAIT(0); }
        __syncthreads();
        uint32_t ab = AB0 + (s & 1) * 32768, bb = BB0 + (s & 1) * 32768;
#pragma unroll
        for (int k16 = 0; k16 < 8; k16++) {
            uint32_t a[2][4];
#pragma unroll
            for (int mt = 0; mt < 2; mt++) {
                int row = wm * 32 + mt * 16 + (lane & 15);
                int ch  = k16 * 2 + (lane >> 4);
                ldsm4(a[mt], ab + row * 256 + ((ch ^ (row & 7)) << 4));
            }
            uint32_t bq[4][4];
#pragma unroll
            for (int np = 0; np < 4; np++) {
                int row = wn * 64 + np * 16 + (lane & 7) + ((lane >> 4) << 3);
                int ch  = k16 * 2 + ((lane >> 3) & 1);
                ldsm4(bq[np], bb + row * 256 + ((ch ^ (row & 7)) << 4));
            }
#pragma unroll
            for (int mt = 0; mt < 2; mt++)
#pragma unroll
                for (int np = 0; np < 4; np++) {
                    mma_f16(acc[mt][2 * np],     a[mt], bq[np][0], bq[np][1]);
                    mma_f16(acc[mt][2 * np + 1], a[mt], bq[np][2], bq[np][3]);
                }
        }
        __syncthreads();
    }
    // epilogue: + bias; K -> fp16, V -> bf16
#pragma unroll
    for (int mt = 0; mt < 2; mt++) {
        int r0 = m0 + wm * 32 + mt * 16 + (lane >> 2);
#pragma unroll
        for (int half = 0; half < 2; half++) {
            int rr = r0 + half * 8;
#pragma unroll
            for (int nt = 0; nt < 8; nt++) {
                int col = wn * 64 + nt * 8 + (lane & 3) * 2;
                float b0 = (NTAPS == 9) ? bias_v[c0 + col]     : g_kbias[c0 + col];
                float b1 = (NTAPS == 9) ? bias_v[c0 + col + 1] : g_kbias[c0 + col + 1];
                float v0 = acc[mt][nt][half * 2] + b0;
                float v1 = acc[mt][nt][half * 2 + 1] + b1;
                if (NTAPS == 1) {
                    __half2 h = __floats2half2_rn(v0, v1);
                    *(uint32_t*)(g_Kh + ((size_t)b * NPIX + rr) * COUT + c0 + col) = *(uint32_t*)&h;
                } else {
                    __nv_bfloat162 h = __floats2bfloat162_rn(v0, v1);
                    *(uint32_t*)(g_V + ((size_t)b * NPIX + rr) * COUT + c0 + col) = *(uint32_t*)&h;
                }
            }
        }
    }
}

// ---------------- fused flash attention (split-K, no max-shift) -------------------
// S phase fp16 (accurate logits); PV phase bf16 (P can exceed fp16 range).
__global__ __launch_bounds__(256) void flash_kernel() {
    extern __shared__ unsigned char smem[];
    const uint32_t sb = smem_u32(smem);
    const uint32_t KB = sb;                  // 2 x 32768
    const uint32_t VB = sb + 65536;          // 2 x 65536
    const uint32_t PB = sb + 65536 + 131072; // 16384
    float* psum = (float*)(smem + 65536 + 131072 + 16384);  // [2][64]

    int tid = threadIdx.x, lane = tid & 31, wid = tid >> 5;
    int wm = wid & 3, wn = wid >> 2;   // S phase: 4m x 2n
    int pm = wid & 1, pc = wid >> 1;   // PV phase: 2m x 4c
    int b = blockIdx.z, q0 = blockIdx.x * QT, split = blockIdx.y;
    int kbase = split * KCH;

    const __half* Kb = g_Kh + (size_t)b * NPIX * CK;
    const __nv_bfloat16* Vb = g_V + (size_t)b * NPIX * CV;

    // ---- stage Kq (64x128) into V-buf1 area; load resident A fragments ----
#pragma unroll
    for (int i = 0; i < 4; i++) {
        int idx = tid + i * 256;
        int row = idx >> 4, ch = idx & 15;
        cpa16(VB + 65536 + row * 256 + ((ch ^ (row & 7)) << 4),
              Kb + (size_t)(q0 + row) * CK + ch * 8, 16);
    }
    CP_COMMIT();
    CP_WAIT(0);
    __syncthreads();
    uint32_t aq[8][4];
    {
        int row = wm * 16 + (lane & 15);
#pragma unroll
        for (int k16 = 0; k16 < 8; k16++) {
            int ch = k16 * 2 + (lane >> 4);
            ldsm4(aq[k16], VB + 65536 + row * 256 + ((ch ^ (row & 7)) << 4));
        }
    }

    auto load_kv = [&](int it, int buf) {
        uint32_t kb = KB + buf * 32768, vb = VB + buf * 65536;
        int base = kbase + it * KT;
#pragma unroll
        for (int i = 0; i < 8; i++) {
            int idx = tid + i * 256;
            int row = idx >> 4, ch = idx & 15;
            cpa16(kb + row * 256 + ((ch ^ (row & 7)) << 4),
                  Kb + (size_t)(base + row) * CK + ch * 8, 16);
        }
#pragma unroll
        for (int i = 0; i < 16; i++) {
            int idx = tid + i * 256;
            int row = idx >> 5, ch = idx & 31;
            cpa16(vb + row * 512 + ((ch ^ (row & 7)) << 4),
                  Vb + (size_t)(base + row) * CV + ch * 8, 16);
        }
    };

    float acc[2][8][4] = {};
    float ps0 = 0.f, ps1 = 0.f;
    int r0t = wm * 16 + (lane >> 2);
    int r1t = r0t + 8;

    load_kv(0, 0);
    CP_COMMIT();

    for (int it = 0; it < NIT; it++) {
        int buf = it & 1;
        __syncthreads();
        if (it + 1 < NIT) load_kv(it + 1, buf ^ 1);
        CP_COMMIT();
        CP_WAIT(1);
        __syncthreads();

        uint32_t kb = KB + buf * 32768, vb = VB + buf * 65536;

        // ---- S = Kq @ Kk^T (fp16 operands) ----
        float sacc[8][4] = {};
#pragma unroll
        for (int k16 = 0; k16 < 8; k16++) {
#pragma unroll
            for (int np = 0; np < 4; np++) {
                int row = wn * 64 + np * 16 + (lane & 7) + ((lane >> 4) << 3);
                int ch  = k16 * 2 + ((lane >> 3) & 1);
                uint32_t bq[4];
                ldsm4(bq, kb + row * 256 + ((ch ^ (row & 7)) << 4));
                mma_f16(sacc[2 * np],     aq[k16], bq[0], bq[1]);
                mma_f16(sacc[2 * np + 1], aq[k16], bq[2], bq[3]);
            }
        }

        // ---- P = exp(S); row sums; write P bf16 ----
#pragma unroll
        for (int np = 0; np < 4; np++) {
#pragma unroll
            for (int j = 0; j < 2; j++) {
                float* s = sacc[2 * np + j];
                float e0 = __expf(s[0]), e1 = __expf(s[1]);
                float e2 = __expf(s[2]), e3 = __expf(s[3]);
                ps0 += e0 + e1;
                ps1 += e2 + e3;
                int chunk = wn * 8 + np * 2 + j;
                int cb = (lane & 3) * 4;
                __nv_bfloat162 h0 = __floats2bfloat162_rn(e0, e1);
                __nv_bfloat162 h1 = __floats2bfloat162_rn(e2, e3);
                *(uint32_t*)(smem + (PB - sb) + r0t * 256 + ((chunk ^ (r0t & 7)) << 4) + cb) = *(uint32_t*)&h0;
                *(uint32_t*)(smem + (PB - sb) + r1t * 256 + ((chunk ^ (r1t & 7)) << 4) + cb) = *(uint32_t*)&h1;
            }
        }
        __syncthreads();

        // ---- PV: acc += P @ V (bf16) ----
        {
            int prowb = pm * 32 + (lane & 15);
#pragma unroll
            for (int k16 = 0; k16 < 8; k16++) {
                uint32_t ap[2][4];
                int ch = k16 * 2 + (lane >> 4);
                ldsm4(ap[0], PB + prowb * 256 + ((ch ^ (prowb & 7)) << 4));
                ldsm4(ap[1], PB + (prowb + 16) * 256 + ((ch ^ ((prowb + 16) & 7)) << 4));
                int krow = k16 * 16 + (lane & 7) + ((lane >> 3) & 1) * 8;
#pragma unroll
                for (int np = 0; np < 4; np++) {
                    int nch = pc * 8 + np * 2 + (lane >> 4);
                    uint32_t bq[4];
                    ldsm4t(bq, vb + krow * 512 + ((nch ^ (krow & 7)) << 4));
                    mma_bf16(acc[0][2 * np],     ap[0], bq[0], bq[1]);
                    mma_bf16(acc[0][2 * np + 1], ap[0], bq[2], bq[3]);
                    mma_bf16(acc[1][2 * np],     ap[1], bq[0], bq[1]);
                    mma_bf16(acc[1][2 * np + 1], ap[1], bq[2], bq[3]);
                }
            }
        }
    }

    // ---- epilogue: reduce l, write partials ----
    ps0 += __shfl_xor_sync(0xffffffff, ps0, 1);
    ps0 += __shfl_xor_sync(0xffffffff, ps0, 2);
    ps1 += __shfl_xor_sync(0xffffffff, ps1, 1);
    ps1 += __shfl_xor_sync(0xffffffff, ps1, 2);
    if ((lane & 3) == 0) {
        psum[wn * 64 + r0t] = ps0;
        psum[wn * 64 + r1t] = ps1;
    }
    __syncthreads();
    if (tid < 64)
        g_l[(b * NSPLIT + split) * NPIX + q0 + tid] = psum[tid] + psum[64 + tid];

    float* op = g_part + ((size_t)(b * NSPLIT + split) * NPIX + q0) * CV;
#pragma unroll
    for (int mt = 0; mt < 2; mt++) {
        int r = pm * 32 + mt * 16 + (lane >> 2);
#pragma unroll
        for (int n8 = 0; n8 < 8; n8++) {
            int col = pc * 64 + n8 * 8 + (lane & 3) * 2;
            *(float2*)(op + (size_t)r * CV + col)       = make_float2(acc[mt][n8][0], acc[mt][n8][1]);
            *(float2*)(op + (size_t)(r + 8) * CV + col) = make_float2(acc[mt][n8][2], acc[mt][n8][3]);
        }
    }
}

// ---------------- combine: ctx = (o0 + o1) / (l0 + l1) -> fp16 --------------------
__global__ void combine_kernel() {
    int idx = blockIdx.x * 4 + (threadIdx.x >> 6);
    int b = idx / NPIX, n = idx - b * NPIX;
    int c = (threadIdx.x & 63) * 4;
    float l0 = g_l[(b * NSPLIT + 0) * NPIX + n];
    float l1 = g_l[(b * NSPLIT + 1) * NPIX + n];
    float inv = 1.0f / (l0 + l1);
    const float* p0 = g_part + ((size_t)(b * NSPLIT + 0) * NPIX + n) * CV + c;
    const float* p1 = g_part + ((size_t)(b * NSPLIT + 1) * NPIX + n) * CV + c;
    float4 a = *(const float4*)p0;
    float4 bb = *(const float4*)p1;
    __half2 h0 = __floats2half2_rn((a.x + bb.x) * inv, (a.y + bb.y) * inv);
    __half2 h1 = __floats2half2_rn((a.z + bb.z) * inv, (a.w + bb.w) * inv);
    uint2 v;
    v.x = *(uint32_t*)&h0; v.y = *(uint32_t*)&h1;
    *(uint2*)(g_ctxh + ((size_t)b * NPIX + n) * CV + c) = v;
}

// ---------------- out[b][co][n] = ww @ ctx^T + bw + x (f16 mma) -------------------
// A = wwh[co][c] (128x256), B = ctxh[n][c] (128x256), single-shot K=256.
__global__ __launch_bounds__(256) void gemm_out_kernel(const float* __restrict__ bw,
                                                       const float* __restrict__ x,
                                                       float* __restrict__ out) {
    extern __shared__ unsigned char smem[];
    uint32_t sb = smem_u32(smem);
    const uint32_t SA = sb, SB = sb + 65536;

    int tid = threadIdx.x, lane = tid & 31, wid = tid >> 5;
    int wm = wid & 3, wn = wid >> 2;
    int b = blockIdx.z, co0 = blockIdx.y * 128, n0 = blockIdx.x * 128;

#pragma unroll
    for (int i = 0; i < 16; i++) {
        int idx = tid + i * 256;
        int row = idx >> 5, ch = idx & 31;
        uint32_t soff = row * 512 + ((ch ^ (row & 7)) << 4);
        cpa16(SA + soff, g_wwh + (size_t)(co0 + row) * CV + ch * 8, 16);
        cpa16(SB + soff, g_ctxh + ((size_t)b * NPIX + n0 + row) * CV + ch * 8, 16);
    }
    CP_COMMIT();
    CP_WAIT(0);
    __syncthreads();

    float acc[2][8][4] = {};
#pragma unroll
    for (int k16 = 0; k16 < 16; k16++) {
        uint32_t a[2][4];
#pragma unroll
        for (int mt = 0; mt < 2; mt++) {
            int row = wm * 32 + mt * 16 + (lane & 15);
            int ch  = k16 * 2 + (lane >> 4);
            ldsm4(a[mt], SA + row * 512 + ((ch ^ (row & 7)) << 4));
        }
        uint32_t bq[4][4];
#pragma unroll
        for (int np = 0; np < 4; np++) {
            int row = wn * 64 + np * 16 + (lane & 7) + ((lane >> 4) << 3);
            int ch  = k16 * 2 + ((lane >> 3) & 1);
            ldsm4(bq[np], SB + row * 512 + ((ch ^ (row & 7)) << 4));
        }
#pragma unroll
        for (int mt = 0; mt < 2; mt++)
#pragma unroll
            for (int np = 0; np < 4; np++) {
                mma_f16(acc[mt][2 * np],     a[mt], bq[np][0], bq[np][1]);
                mma_f16(acc[mt][2 * np + 1], a[mt], bq[np][2], bq[np][3]);
            }
    }
    // epilogue: out[co][n] = acc + bw[co] + x[co][n]
#pragma unroll
    for (int mt = 0; mt < 2; mt++) {
#pragma unroll
        for (int half = 0; half < 2; half++) {
            int co = co0 + wm * 32 + mt * 16 + (lane >> 2) + half * 8;
            float bwv = bw[co];
            size_t xb = ((size_t)b * CIN + co) * NPIX + n0;
            size_t ob = ((size_t)b * CV  + co) * NPIX + n0;
#pragma unroll
            for (int n8 = 0; n8 < 8; n8++) {
                int col = wn * 64 + n8 * 8 + (lane & 3) * 2;
                float2 xv = *(const float2*)(x + xb + col);
                float2 o;
                o.x = acc[mt][n8][half * 2]     + bwv + xv.x;
                o.y = acc[mt][n8][half * 2 + 1] + bwv + xv.y;
                *(float2*)(out + ob + col) = o;
            }
        }
    }
}

// ---------------- launch ----------------------------------------------------------
extern "C" void kernel_launch(void* const* d_in, const int* in_sizes, int n_in,
                              void* d_out, int out_size) {
    (void)in_sizes; (void)n_in; (void)out_size;
    const float* x     = (const float*)d_in[0];
    const float* wk    = (const float*)d_in[1];
    const float* bk    = (const float*)d_in[2];
    const float* gamma = (const float*)d_in[3];
    const float* beta  = (const float*)d_in[4];
    const float* rmean = (const float*)d_in[5];
    const float* rvar  = (const float*)d_in[6];
    const float* wv    = (const float*)d_in[7];
    const float* bv    = (const float*)d_in[8];
    const float* ww    = (const float*)d_in[9];
    const float* bw    = (const float*)d_in[10];
    float* out = (float*)d_out;

    const int CONV_SMEM = 131072;
    const int OUT_SMEM = 131072;
    const int FLASH_SMEM = 65536 + 131072 + 16384 + 512;  // 213504
    cudaFuncSetAttribute(conv_mma_kernel<CK, 1>, cudaFuncAttributeMaxDynamicSharedMemorySize, CONV_SMEM);
    cudaFuncSetAttribute(conv_mma_kernel<CV, 9>, cudaFuncAttributeMaxDynamicSharedMemorySize, CONV_SMEM);
    cudaFuncSetAttribute(flash_kernel, cudaFuncAttributeMaxDynamicSharedMemorySize, FLASH_SMEM);
    cudaFuncSetAttribute(gemm_out_kernel, cudaFuncAttributeMaxDynamicSharedMemorySize, OUT_SMEM);

    prep_kernel<<<256, 256>>>(wk, bk, gamma, beta, rmean, rvar, wv, ww);
    transpose_x_kernel<<<dim3(NPIX / 32, CIN / 32, 2), 256>>>(x);
    conv_mma_kernel<CK, 1><<<dim3(1, NPIX / 128, 2), 256, CONV_SMEM>>>(bv);
    conv_mma_kernel<CV, 9><<<dim3(CV / 128, NPIX / 128, 2), 256, CONV_SMEM>>>(bv);
    flash_kernel<<<dim3(NPIX / QT, NSPLIT, 2), 256, FLASH_SMEM>>>();
    combine_kernel<<<2 * NPIX / 4, 256>>>();
    gemm_out_kernel<<<dim3(NPIX / 128, CV / 128, 2), 256, OUT_SMEM>>>(bw, x, out);
}

// round 8
// speedup vs baseline: 1.4945x; 1.0004x over previous
#include <cuda_runtime.h>
#include <cuda_bf16.h>
#include <cuda_fp16.h>
#include <stdint.h>

#define NPIX 6400
#define IMGW 80
#define CIN 256
#define CK 128
#define CV 256
#define QT 64
#define KT 128
#define NSPLIT 2
#define KCH (NPIX / NSPLIT)
#define NIT (KCH / KT)
#define SQRT_LOG2E 1.2011224087864498f

// ---------------- scratch ----------------
__device__ __half g_xT[(size_t)2 * NPIX * CIN];
__device__ __half g_Kh[(size_t)2 * NPIX * CK];   // K pre-scaled by sqrt(log2e)
__device__ __nv_bfloat16 g_V[(size_t)2 * NPIX * CV];
__device__ float g_part[(size_t)2 * NSPLIT * NPIX * CV];
__device__ float g_l[2 * NSPLIT * NPIX];
__device__ __half g_ctxh[(size_t)2 * NPIX * CV];
__device__ float g_kbias[CK];
__device__ __half g_wkh[CK * CIN];
__device__ __half g_wvh[9 * CV * CIN];
__device__ __half g_wwh[CV * CV];

// ---------------- PTX helpers ----------------
__device__ __forceinline__ uint32_t smem_u32(const void* p) {
    uint32_t a;
    asm("{ .reg .u64 t; cvta.to.shared.u64 t, %1; cvt.u32.u64 %0, t; }" : "=r"(a) : "l"(p));
    return a;
}
__device__ __forceinline__ void ldsm4(uint32_t* r, uint32_t addr) {
    asm volatile("ldmatrix.sync.aligned.m8n8.x4.shared.b16 {%0,%1,%2,%3}, [%4];"
                 : "=r"(r[0]), "=r"(r[1]), "=r"(r[2]), "=r"(r[3]) : "r"(addr));
}
__device__ __forceinline__ void ldsm4t(uint32_t* r, uint32_t addr) {
    asm volatile("ldmatrix.sync.aligned.m8n8.x4.trans.shared.b16 {%0,%1,%2,%3}, [%4];"
                 : "=r"(r[0]), "=r"(r[1]), "=r"(r[2]), "=r"(r[3]) : "r"(addr));
}
__device__ __forceinline__ void mma_bf16(float* c, const uint32_t* a, uint32_t b0, uint32_t b1) {
    asm volatile("mma.sync.aligned.m16n8k16.row.col.f32.bf16.bf16.f32 "
                 "{%0,%1,%2,%3}, {%4,%5,%6,%7}, {%8,%9}, {%0,%1,%2,%3};"
                 : "+f"(c[0]), "+f"(c[1]), "+f"(c[2]), "+f"(c[3])
                 : "r"(a[0]), "r"(a[1]), "r"(a[2]), "r"(a[3]), "r"(b0), "r"(b1));
}
__device__ __forceinline__ void mma_f16(float* c, const uint32_t* a, uint32_t b0, uint32_t b1) {
    asm volatile("mma.sync.aligned.m16n8k16.row.col.f32.f16.f16.f32 "
                 "{%0,%1,%2,%3}, {%4,%5,%6,%7}, {%8,%9}, {%0,%1,%2,%3};"
                 : "+f"(c[0]), "+f"(c[1]), "+f"(c[2]), "+f"(c[3])
                 : "r"(a[0]), "r"(a[1]), "r"(a[2]), "r"(a[3]), "r"(b0), "r"(b1));
}
__device__ __forceinline__ void cpa16(uint32_t dst, const void* src, int sz) {
    asm volatile("cp.async.cg.shared.global [%0], [%1], 16, %2;"
                 :: "r"(dst), "l"(src), "r"(sz));
}
#define CP_COMMIT() asm volatile("cp.async.commit_group;" ::: "memory")
#define CP_WAIT(n)  asm volatile("cp.async.wait_group %0;" :: "n"(n) : "memory")
__device__ __forceinline__ void bar_sync(int id, int cnt) {
    asm volatile("bar.sync %0, %1;" :: "r"(id), "r"(cnt) : "memory");
}
__device__ __forceinline__ void bar_arrive(int id, int cnt) {
    asm volatile("bar.arrive %0, %1;" :: "r"(id), "r"(cnt) : "memory");
}

// ---------------- weight prep (fp16) ----------------
__global__ void prep_kernel(const float* __restrict__ wk, const float* __restrict__ bk,
                            const float* __restrict__ gamma, const float* __restrict__ beta,
                            const float* __restrict__ rmean, const float* __restrict__ rvar,
                            const float* __restrict__ wv, const float* __restrict__ ww) {
    int tid = blockIdx.x * blockDim.x + threadIdx.x;
    int nth = gridDim.x * blockDim.x;
    if (tid < CK) {
        float inv = gamma[tid] * rsqrtf(rvar[tid] + 1e-5f);
        g_kbias[tid] = bk[tid] * inv + beta[tid] - rmean[tid] * inv;
    }
    for (int idx = tid; idx < CK * CIN; idx += nth) {
        int c = idx / CIN;
        float inv = gamma[c] * rsqrtf(rvar[c] + 1e-5f);
        g_wkh[idx] = __float2half(wk[idx] * inv);
    }
    for (int idx = tid; idx < CV * CV; idx += nth)
        g_wwh[idx] = __float2half(ww[idx]);
    for (int idx = tid; idx < 9 * CV * CIN; idx += nth) {
        int t = idx / (CV * CIN);
        int rem = idx - t * CV * CIN;
        int o = rem / CIN;
        int i = rem - o * CIN;
        g_wvh[idx] = __float2half(wv[(o * CIN + i) * 9 + t]);
    }
}

// ---------------- x transpose: [b][c][n] fp32 -> [b][n][c] fp16 -------------------
__global__ void transpose_x_kernel(const float* __restrict__ x) {
    __shared__ float t[32][33];
    int b = blockIdx.z, n0 = blockIdx.x * 32, c0 = blockIdx.y * 32;
    int tid = threadIdx.x, nl = tid & 31, cg = tid >> 5;
#pragma unroll
    for (int i = 0; i < 4; i++) {
        int c = cg + i * 8;
        t[c][nl] = x[((size_t)b * CIN + c0 + c) * NPIX + n0 + nl];
    }
    __syncthreads();
    __half2 h0 = __floats2half2_rn(t[cg * 4 + 0][nl], t[cg * 4 + 1][nl]);
    __half2 h1 = __floats2half2_rn(t[cg * 4 + 2][nl], t[cg * 4 + 3][nl]);
    uint2 v;
    v.x = *(uint32_t*)&h0; v.y = *(uint32_t*)&h1;
    *(uint2*)(g_xT + ((size_t)b * NPIX + n0 + nl) * CIN + c0 + cg * 4) = v;
}

// ---------------- conv as implicit NT GEMM (fp16 mma, BM=64, BK=128) --------------
template <int COUT, int NTAPS>
__global__ __launch_bounds__(256) void conv_mma_kernel(const float* __restrict__ bias_v) {
    extern __shared__ unsigned char smem[];
    uint32_t sb = smem_u32(smem);
    const uint32_t AB0 = sb, BB0 = sb + 32768;   // A: 2x16KB, B: 2x32KB

    int tid = threadIdx.x, lane = tid & 31, wid = tid >> 5;
    int wm = wid & 3, wn = wid >> 2;             // 4m x 2n over 64x128
    int b = blockIdx.z, m0 = blockIdx.y * 64, c0 = blockIdx.x * 128;

    const __half* xTb = g_xT + (size_t)b * NPIX * CIN;
    const __half* wb  = (NTAPS == 9) ? g_wvh : g_wkh;

    int lch = tid & 15;
    int ay[4], ax[4];
#pragma unroll
    for (int i = 0; i < 4; i++) {
        int row = (tid >> 4) + i * 16;
        int p = m0 + row;
        ay[i] = p / IMGW;
        ax[i] = p - ay[i] * IMGW;
    }

    const int NS = NTAPS * 2;
    auto load_stage = [&](int s, int buf) {
        int tap = (NTAPS == 9) ? (s >> 1) : 0;
        int kc  = s & 1;
        int dy = (NTAPS == 9) ? (tap / 3 - 1) : 0;
        int dx = (NTAPS == 9) ? (tap % 3 - 1) : 0;
        int off = dy * IMGW + dx;
        uint32_t ab = AB0 + buf * 16384, bb = BB0 + buf * 32768;
#pragma unroll
        for (int i = 0; i < 4; i++) {
            int row = (tid >> 4) + i * 16;
            bool valid = (NTAPS == 1) ||
                         (((unsigned)(ay[i] + dy) < (unsigned)IMGW) &&
                          ((unsigned)(ax[i] + dx) < (unsigned)IMGW));
            int srow = m0 + row + (valid ? off : 0);
            cpa16(ab + row * 256 + ((lch ^ (row & 7)) << 4),
                  xTb + (size_t)srow * CIN + kc * 128 + lch * 8, valid ? 16 : 0);
        }
#pragma unroll
        for (int i = 0; i < 8; i++) {
            int idx = tid + i * 256;
            int row = idx >> 4, ch = idx & 15;
            cpa16(bb + row * 256 + ((ch ^ (row & 7)) << 4),
                  wb + (size_t)(tap * COUT + c0 + row) * CIN + kc * 128 + ch * 8, 16);
        }
        CP_COMMIT();
    };

    float acc[8][4] = {};
    load_stage(0, 0);
    for (int s = 0; s < NS; s++) {
        if (s + 1 < NS) { load_stage(s + 1, (s + 1) & 1); CP_WAIT(1); }
        else            { CP_WAIT(0); }
        __syncthreads();
        uint32_t ab = AB0 + (s & 1) * 16384, bb = BB0 + (s & 1) * 32768;
#pragma unroll
        for (int k16 = 0; k16 < 8; k16++) {
            uint32_t a[4];
            {
                int row = wm * 16 + (lane & 15);
                int ch  = k16 * 2 + (lane >> 4);
                ldsm4(a, ab + row * 256 + ((ch ^ (row & 7)) << 4));
            }
            uint32_t bq[4][4];
#pragma unroll
            for (int np = 0; np < 4; np++) {
                int row = wn * 64 + np * 16 + (lane & 7) + ((lane >> 4) << 3);
                int ch  = k16 * 2 + ((lane >> 3) & 1);
                ldsm4(bq[np], bb + row * 256 + ((ch ^ (row & 7)) << 4));
            }
#pragma unroll
            for (int np = 0; np < 4; np++) {
                mma_f16(acc[2 * np],     a, bq[np][0], bq[np][1]);
                mma_f16(acc[2 * np + 1], a, bq[np][2], bq[np][3]);
            }
        }
        __syncthreads();
    }
    // epilogue: K scaled by sqrt(log2e) so S = log2e * (K.Kq) with no extra rounding
    int r0 = m0 + wm * 16 + (lane >> 2);
#pragma unroll
    for (int half = 0; half < 2; half++) {
        int rr = r0 + half * 8;
#pragma unroll
        for (int nt = 0; nt < 8; nt++) {
            int col = wn * 64 + nt * 8 + (lane & 3) * 2;
            float b0 = (NTAPS == 9) ? bias_v[c0 + col]     : g_kbias[c0 + col];
            float b1 = (NTAPS == 9) ? bias_v[c0 + col + 1] : g_kbias[c0 + col + 1];
            float v0 = acc[nt][half * 2] + b0;
            float v1 = acc[nt][half * 2 + 1] + b1;
            if (NTAPS == 1) {
                __half2 h = __floats2half2_rn(v0 * SQRT_LOG2E, v1 * SQRT_LOG2E);
                *(uint32_t*)(g_Kh + ((size_t)b * NPIX + rr) * COUT + c0 + col) = *(uint32_t*)&h;
            } else {
                __nv_bfloat162 h = __floats2bfloat162_rn(v0, v1);
                *(uint32_t*)(g_V + ((size_t)b * NPIX + rr) * COUT + c0 + col) = *(uint32_t*)&h;
            }
        }
    }
}

// ---------------- warp-specialized flash attention --------------------------------
// 384 threads: warps 0-3 = S-group (QK^T + exp2 + P store), warps 4-11 = PV-group.
// Group-local syncs are issued BEFORE the next-stage cp.async (overwrite hazard).
#define BFULL0 1
#define BEMPTY0 3
#define BSLOC 5
#define BPVLOC 6
__global__ __launch_bounds__(384) void flash_kernel() {
    extern __shared__ unsigned char smem[];
    const uint32_t sb = smem_u32(smem);
    const uint32_t KB0 = sb;                       // 2 x 32768
    const uint32_t VB0 = sb + 65536;               // 2 x 65536
    const uint32_t PB0 = sb + 65536 + 131072;      // 2 x 16384

    int tid = threadIdx.x, lane = tid & 31, wid = tid >> 5;
    int b = blockIdx.z, q0 = blockIdx.x * QT, split = blockIdx.y;
    int kbase = split * KCH;

    const __half* Kb = g_Kh + (size_t)b * NPIX * CK;
    const __nv_bfloat16* Vb = g_V + (size_t)b * NPIX * CV;

    if (wid < 4) {
        // ================= S-group (128 threads) =================
#pragma unroll
        for (int i = 0; i < 8; i++) {
            int idx = tid + i * 128;
            int row = idx >> 4, ch = idx & 15;
            cpa16(PB0 + row * 256 + ((ch ^ (row & 7)) << 4),
                  Kb + (size_t)(q0 + row) * CK + ch * 8, 16);
        }
        CP_COMMIT();
#pragma unroll
        for (int i = 0; i < 16; i++) {
            int idx = tid + i * 128;
            int row = idx >> 4, ch = idx & 15;
            cpa16(KB0 + row * 256 + ((ch ^ (row & 7)) << 4),
                  Kb + (size_t)(kbase + row) * CK + ch * 8, 16);
        }
        CP_COMMIT();
        CP_WAIT(1);                    // Kq done (K0 may still be in flight)
        bar_sync(BSLOC, 128);

        uint32_t aq[8][4];
        {
            int row = wid * 16 + (lane & 15);
#pragma unroll
            for (int k16 = 0; k16 < 8; k16++) {
                int ch = k16 * 2 + (lane >> 4);
                ldsm4(aq[k16], PB0 + row * 256 + ((ch ^ (row & 7)) << 4));
            }
        }

        float ps0 = 0.f, ps1 = 0.f;
        for (int it = 0; it < NIT; it++) {
            int buf = it & 1;
            if (it + 1 < NIT) {
                bar_sync(BSLOC, 128);  // all S-warps done reading K buf^1 (and aq at it=0)
#pragma unroll
                for (int i = 0; i < 16; i++) {
                    int idx = tid + i * 128;
                    int row = idx >> 4, ch = idx & 15;
                    cpa16(KB0 + (buf ^ 1) * 32768 + row * 256 + ((ch ^ (row & 7)) << 4),
                          Kb + (size_t)(kbase + (it + 1) * KT + row) * CK + ch * 8, 16);
                }
                CP_COMMIT();
                CP_WAIT(1);
            } else {
                CP_WAIT(0);
            }
            bar_sync(BSLOC, 128);      // K buf visible to all S-warps

            uint32_t kb = KB0 + buf * 32768;
            float sacc[16][4] = {};
#pragma unroll
            for (int k16 = 0; k16 < 8; k16++) {
#pragma unroll
                for (int np = 0; np < 8; np++) {
                    int row = np * 16 + (lane & 7) + ((lane >> 4) << 3);
                    int ch  = k16 * 2 + ((lane >> 3) & 1);
                    uint32_t bq[4];
                    ldsm4(bq, kb + row * 256 + ((ch ^ (row & 7)) << 4));
                    mma_f16(sacc[2 * np],     aq[k16], bq[0], bq[1]);
                    mma_f16(sacc[2 * np + 1], aq[k16], bq[2], bq[3]);
                }
            }

            if (it >= 2) bar_sync(BEMPTY0 + buf, 384);   // PV consumed P buf (it-2)

            uint32_t pb = PB0 + buf * 16384;
            int prow0 = wid * 16 + (lane >> 2), prow1 = prow0 + 8;
            int cb = (lane & 3) * 4;
#pragma unroll
            for (int f = 0; f < 16; f++) {
                float* s = sacc[f];
                float e0 = exp2f(s[0]), e1 = exp2f(s[1]);
                float e2 = exp2f(s[2]), e3 = exp2f(s[3]);
                ps0 += e0 + e1;
                ps1 += e2 + e3;
                __nv_bfloat162 h0 = __floats2bfloat162_rn(e0, e1);
                __nv_bfloat162 h1 = __floats2bfloat162_rn(e2, e3);
                *(uint32_t*)(smem + (pb - sb) + prow0 * 256 + ((f ^ (prow0 & 7)) << 4) + cb) = *(uint32_t*)&h0;
                *(uint32_t*)(smem + (pb - sb) + prow1 * 256 + ((f ^ (prow1 & 7)) << 4) + cb) = *(uint32_t*)&h1;
            }
            bar_arrive(BFULL0 + buf, 384);
        }
        // absorb last two EMPTY arrivals
        bar_sync(BEMPTY0 + ((NIT - 2) & 1), 384);
        bar_sync(BEMPTY0 + ((NIT - 1) & 1), 384);

        ps0 += __shfl_xor_sync(0xffffffff, ps0, 1);
        ps0 += __shfl_xor_sync(0xffffffff, ps0, 2);
        ps1 += __shfl_xor_sync(0xffffffff, ps1, 1);
        ps1 += __shfl_xor_sync(0xffffffff, ps1, 2);
        if ((lane & 3) == 0) {
            int base = (b * NSPLIT + split) * NPIX + q0 + wid * 16 + (lane >> 2);
            g_l[base]     = ps0;
            g_l[base + 8] = ps1;
        }
    } else {
        // ================= PV-group (256 threads) =================
        int pvtid = tid - 128;
        int pvid = wid - 4;
        int pm = pvid & 1, pc = pvid >> 1;

        auto load_v = [&](int it, int buf) {
#pragma unroll
            for (int i = 0; i < 16; i++) {
                int idx = pvtid + i * 256;
                int row = idx >> 5, ch = idx & 31;
                cpa16(VB0 + buf * 65536 + row * 512 + ((ch ^ (row & 7)) << 4),
                      Vb + (size_t)(kbase + it * KT + row) * CV + ch * 8, 16);
            }
            CP_COMMIT();
        };

        float acc[2][8][4] = {};
        load_v(0, 0);
        for (int it = 0; it < NIT; it++) {
            int buf = it & 1;
            if (it + 1 < NIT) {
                bar_sync(BPVLOC, 256);   // all PV warps done reading V buf^1 (iter it-1)
                load_v(it + 1, buf ^ 1);
                CP_WAIT(1);
            } else {
                CP_WAIT(0);
            }
            bar_sync(BPVLOC, 256);       // V buf visible
            bar_sync(BFULL0 + buf, 384); // P buf ready

            uint32_t pb = PB0 + buf * 16384, vb = VB0 + buf * 65536;
            int prowb = pm * 32 + (lane & 15);
#pragma unroll
            for (int k16 = 0; k16 < 8; k16++) {
                uint32_t ap[2][4];
                int ch = k16 * 2 + (lane >> 4);
                ldsm4(ap[0], pb + prowb * 256 + ((ch ^ (prowb & 7)) << 4));
                ldsm4(ap[1], pb + (prowb + 16) * 256 + ((ch ^ ((prowb + 16) & 7)) << 4));
                int krow = k16 * 16 + (lane & 7) + ((lane >> 3) & 1) * 8;
#pragma unroll
                for (int np = 0; np < 4; np++) {
                    int nch = pc * 8 + np * 2 + (lane >> 4);
                    uint32_t bq[4];
                    ldsm4t(bq, vb + krow * 512 + ((nch ^ (krow & 7)) << 4));
                    mma_bf16(acc[0][2 * np],     ap[0], bq[0], bq[1]);
                    mma_bf16(acc[0][2 * np + 1], ap[0], bq[2], bq[3]);
                    mma_bf16(acc[1][2 * np],     ap[1], bq[0], bq[1]);
                    mma_bf16(acc[1][2 * np + 1], ap[1], bq[2], bq[3]);
                }
            }
            bar_arrive(BEMPTY0 + buf, 384);
        }

        float* op = g_part + ((size_t)(b * NSPLIT + split) * NPIX + q0) * CV;
#pragma unroll
        for (int mt = 0; mt < 2; mt++) {
            int r = pm * 32 + mt * 16 + (lane >> 2);
#pragma unroll
            for (int n8 = 0; n8 < 8; n8++) {
                int col = pc * 64 + n8 * 8 + (lane & 3) * 2;
                *(float2*)(op + (size_t)r * CV + col)       = make_float2(acc[mt][n8][0], acc[mt][n8][1]);
                *(float2*)(op + (size_t)(r + 8) * CV + col) = make_float2(acc[mt][n8][2], acc[mt][n8][3]);
            }
        }
    }
}

// ---------------- combine: ctx = (o0 + o1) / (l0 + l1) -> fp16 --------------------
__global__ void combine_kernel() {
    int idx = blockIdx.x * 4 + (threadIdx.x >> 6);
    int b = idx / NPIX, n = idx - b * NPIX;
    int c = (threadIdx.x & 63) * 4;
    float l0 = g_l[(b * NSPLIT + 0) * NPIX + n];
    float l1 = g_l[(b * NSPLIT + 1) * NPIX + n];
    float inv = 1.0f / (l0 + l1);
    const float* p0 = g_part + ((size_t)(b * NSPLIT + 0) * NPIX + n) * CV + c;
    const float* p1 = g_part + ((size_t)(b * NSPLIT + 1) * NPIX + n) * CV + c;
    float4 a = *(const float4*)p0;
    float4 bb = *(const float4*)p1;
    __half2 h0 = __floats2half2_rn((a.x + bb.x) * inv, (a.y + bb.y) * inv);
    __half2 h1 = __floats2half2_rn((a.z + bb.z) * inv, (a.w + bb.w) * inv);
    uint2 v;
    v.x = *(uint32_t*)&h0; v.y = *(uint32_t*)&h1;
    *(uint2*)(g_ctxh + ((size_t)b * NPIX + n) * CV + c) = v;
}

// ---------------- out[b][co][n] = ww @ ctx^T + bw + x (f16 mma) -------------------
__global__ __launch_bounds__(256) void gemm_out_kernel(const float* __restrict__ bw,
                                                       const float* __restrict__ x,
                                                       float* __restrict__ out) {
    extern __shared__ unsigned char smem[];
    uint32_t sb = smem_u32(smem);
    const uint32_t SA = sb, SB = sb + 65536;

    int tid = threadIdx.x, lane = tid & 31, wid = tid >> 5;
    int wm = wid & 3, wn = wid >> 2;
    int b = blockIdx.z, co0 = blockIdx.y * 128, n0 = blockIdx.x * 128;

#pragma unroll
    for (int i = 0; i < 16; i++) {
        int idx = tid + i * 256;
        int row = idx >> 5, ch = idx & 31;
        uint32_t soff = row * 512 + ((ch ^ (row & 7)) << 4);
        cpa16(SA + soff, g_wwh + (size_t)(co0 + row) * CV + ch * 8, 16);
        cpa16(SB + soff, g_ctxh + ((size_t)b * NPIX + n0 + row) * CV + ch * 8, 16);
    }
    CP_COMMIT();
    CP_WAIT(0);
    __syncthreads();

    float acc[2][8][4] = {};
#pragma unroll
    for (int k16 = 0; k16 < 16; k16++) {
        uint32_t a[2][4];
#pragma unroll
        for (int mt = 0; mt < 2; mt++) {
            int row = wm * 32 + mt * 16 + (lane & 15);
            int ch  = k16 * 2 + (lane >> 4);
            ldsm4(a[mt], SA + row * 512 + ((ch ^ (row & 7)) << 4));
        }
        uint32_t bq[4][4];
#pragma unroll
        for (int np = 0; np < 4; np++) {
            int row = wn * 64 + np * 16 + (lane & 7) + ((lane >> 4) << 3);
            int ch  = k16 * 2 + ((lane >> 3) & 1);
            ldsm4(bq[np], SB + row * 512 + ((ch ^ (row & 7)) << 4));
        }
#pragma unroll
        for (int mt = 0; mt < 2; mt++)
#pragma unroll
            for (int np = 0; np < 4; np++) {
                mma_f16(acc[mt][2 * np],     a[mt], bq[np][0], bq[np][1]);
                mma_f16(acc[mt][2 * np + 1], a[mt], bq[np][2], bq[np][3]);
            }
    }
#pragma unroll
    for (int mt = 0; mt < 2; mt++) {
#pragma unroll
        for (int half = 0; half < 2; half++) {
            int co = co0 + wm * 32 + mt * 16 + (lane >> 2) + half * 8;
            float bwv = bw[co];
            size_t xb = ((size_t)b * CIN + co) * NPIX + n0;
            size_t ob = ((size_t)b * CV  + co) * NPIX + n0;
#pragma unroll
            for (int n8 = 0; n8 < 8; n8++) {
                int col = wn * 64 + n8 * 8 + (lane & 3) * 2;
                float2 xv = *(const float2*)(x + xb + col);
                float2 o;
                o.x = acc[mt][n8][half * 2]     + bwv + xv.x;
                o.y = acc[mt][n8][half * 2 + 1] + bwv + xv.y;
                *(float2*)(out + ob + col) = o;
            }
        }
    }
}

// ---------------- launch ----------------------------------------------------------
extern "C" void kernel_launch(void* const* d_in, const int* in_sizes, int n_in,
                              void* d_out, int out_size) {
    (void)in_sizes; (void)n_in; (void)out_size;
    const float* x     = (const float*)d_in[0];
    const float* wk    = (const float*)d_in[1];
    const float* bk    = (const float*)d_in[2];
    const float* gamma = (const float*)d_in[3];
    const float* beta  = (const float*)d_in[4];
    const float* rmean = (const float*)d_in[5];
    const float* rvar  = (const float*)d_in[6];
    const float* wv    = (const float*)d_in[7];
    const float* bv    = (const float*)d_in[8];
    const float* ww    = (const float*)d_in[9];
    const float* bw    = (const float*)d_in[10];
    float* out = (float*)d_out;

    const int CONV_SMEM = 98304;
    const int OUT_SMEM = 131072;
    const int FLASH_SMEM = 65536 + 131072 + 32768;     // 229376
    cudaFuncSetAttribute(conv_mma_kernel<CK, 1>, cudaFuncAttributeMaxDynamicSharedMemorySize, CONV_SMEM);
    cudaFuncSetAttribute(conv_mma_kernel<CV, 9>, cudaFuncAttributeMaxDynamicSharedMemorySize, CONV_SMEM);
    cudaFuncSetAttribute(flash_kernel, cudaFuncAttributeMaxDynamicSharedMemorySize, FLASH_SMEM);
    cudaFuncSetAttribute(gemm_out_kernel, cudaFuncAttributeMaxDynamicSharedMemorySize, OUT_SMEM);

    prep_kernel<<<256, 256>>>(wk, bk, gamma, beta, rmean, rvar, wv, ww);
    transpose_x_kernel<<<dim3(NPIX / 32, CIN / 32, 2), 256>>>(x);
    conv_mma_kernel<CK, 1><<<dim3(1, NPIX / 64, 2), 256, CONV_SMEM>>>(bv);
    conv_mma_kernel<CV, 9><<<dim3(CV / 128, NPIX / 64, 2), 256, CONV_SMEM>>>(bv);
    flash_kernel<<<dim3(NPIX / QT, NSPLIT, 2), 384, FLASH_SMEM>>>();
    combine_kernel<<<2 * NPIX / 4, 256>>>();
    gemm_out_kernel<<<dim3(NPIX / 128, CV / 128, 2), 256, OUT_SMEM>>>(bw, x, out);
}

// round 9
// speedup vs baseline: 1.7157x; 1.1480x over previous
#include <cuda_runtime.h>
#include <cuda_bf16.h>
#include <cuda_fp16.h>
#include <stdint.h>

#define NPIX 6400
#define IMGW 80
#define CIN 256
#define CK 128
#define CV 256
#define QT 64
#define KT 128
#define NSPLIT 2
#define KCH (NPIX / NSPLIT)
#define NIT (KCH / KT)
#define SQRT_LOG2E 1.2011224087864498f

// ---------------- scratch ----------------
__device__ __half g_xT[(size_t)2 * NPIX * CIN];
__device__ __half g_Kh[(size_t)2 * NPIX * CK];   // K pre-scaled by sqrt(log2e)
__device__ __nv_bfloat16 g_V[(size_t)2 * NPIX * CV];
__device__ float g_part[(size_t)2 * NSPLIT * NPIX * CV];
__device__ float g_l[2 * NSPLIT * NPIX];
__device__ __half g_ctxh[(size_t)2 * NPIX * CV];
__device__ float g_kbias[CK];
__device__ __half g_wkh[CK * CIN];
__device__ __half g_wvh[9 * CV * CIN];
__device__ __half g_wwh[CV * CV];

// ---------------- PTX helpers ----------------
__device__ __forceinline__ uint32_t smem_u32(const void* p) {
    uint32_t a;
    asm("{ .reg .u64 t; cvta.to.shared.u64 t, %1; cvt.u32.u64 %0, t; }" : "=r"(a) : "l"(p));
    return a;
}
__device__ __forceinline__ void ldsm4(uint32_t* r, uint32_t addr) {
    asm volatile("ldmatrix.sync.aligned.m8n8.x4.shared.b16 {%0,%1,%2,%3}, [%4];"
                 : "=r"(r[0]), "=r"(r[1]), "=r"(r[2]), "=r"(r[3]) : "r"(addr));
}
__device__ __forceinline__ void ldsm4t(uint32_t* r, uint32_t addr) {
    asm volatile("ldmatrix.sync.aligned.m8n8.x4.trans.shared.b16 {%0,%1,%2,%3}, [%4];"
                 : "=r"(r[0]), "=r"(r[1]), "=r"(r[2]), "=r"(r[3]) : "r"(addr));
}
__device__ __forceinline__ void mma_bf16(float* c, const uint32_t* a, uint32_t b0, uint32_t b1) {
    asm volatile("mma.sync.aligned.m16n8k16.row.col.f32.bf16.bf16.f32 "
                 "{%0,%1,%2,%3}, {%4,%5,%6,%7}, {%8,%9}, {%0,%1,%2,%3};"
                 : "+f"(c[0]), "+f"(c[1]), "+f"(c[2]), "+f"(c[3])
                 : "r"(a[0]), "r"(a[1]), "r"(a[2]), "r"(a[3]), "r"(b0), "r"(b1));
}
__device__ __forceinline__ void mma_f16(float* c, const uint32_t* a, uint32_t b0, uint32_t b1) {
    asm volatile("mma.sync.aligned.m16n8k16.row.col.f32.f16.f16.f32 "
                 "{%0,%1,%2,%3}, {%4,%5,%6,%7}, {%8,%9}, {%0,%1,%2,%3};"
                 : "+f"(c[0]), "+f"(c[1]), "+f"(c[2]), "+f"(c[3])
                 : "r"(a[0]), "r"(a[1]), "r"(a[2]), "r"(a[3]), "r"(b0), "r"(b1));
}
__device__ __forceinline__ void cpa16(uint32_t dst, const void* src, int sz) {
    asm volatile("cp.async.cg.shared.global [%0], [%1], 16, %2;"
                 :: "r"(dst), "l"(src), "r"(sz));
}
#define CP_COMMIT() asm volatile("cp.async.commit_group;" ::: "memory")
#define CP_WAIT(n)  asm volatile("cp.async.wait_group %0;" :: "n"(n) : "memory")
__device__ __forceinline__ void bar_sync(int id, int cnt) {
    asm volatile("bar.sync %0, %1;" :: "r"(id), "r"(cnt) : "memory");
}
__device__ __forceinline__ void bar_arrive(int id, int cnt) {
    asm volatile("bar.arrive %0, %1;" :: "r"(id), "r"(cnt) : "memory");
}
__device__ __forceinline__ float ex2(float x) {
    float y;
    asm("ex2.approx.ftz.f32 %0, %1;" : "=f"(y) : "f"(x));
    return y;
}

// ---------------- weight prep (fp16) ----------------
__global__ void prep_kernel(const float* __restrict__ wk, const float* __restrict__ bk,
                            const float* __restrict__ gamma, const float* __restrict__ beta,
                            const float* __restrict__ rmean, const float* __restrict__ rvar,
                            const float* __restrict__ wv, const float* __restrict__ ww) {
    int tid = blockIdx.x * blockDim.x + threadIdx.x;
    int nth = gridDim.x * blockDim.x;
    if (tid < CK) {
        float inv = gamma[tid] * rsqrtf(rvar[tid] + 1e-5f);
        g_kbias[tid] = bk[tid] * inv + beta[tid] - rmean[tid] * inv;
    }
    for (int idx = tid; idx < CK * CIN; idx += nth) {
        int c = idx / CIN;
        float inv = gamma[c] * rsqrtf(rvar[c] + 1e-5f);
        g_wkh[idx] = __float2half(wk[idx] * inv);
    }
    for (int idx = tid; idx < CV * CV; idx += nth)
        g_wwh[idx] = __float2half(ww[idx]);
    for (int idx = tid; idx < 9 * CV * CIN; idx += nth) {
        int t = idx / (CV * CIN);
        int rem = idx - t * CV * CIN;
        int o = rem / CIN;
        int i = rem - o * CIN;
        g_wvh[idx] = __float2half(wv[(o * CIN + i) * 9 + t]);
    }
}

// ---------------- x transpose: [b][c][n] fp32 -> [b][n][c] fp16 -------------------
__global__ void transpose_x_kernel(const float* __restrict__ x) {
    __shared__ float t[32][33];
    int b = blockIdx.z, n0 = blockIdx.x * 32, c0 = blockIdx.y * 32;
    int tid = threadIdx.x, nl = tid & 31, cg = tid >> 5;
#pragma unroll
    for (int i = 0; i < 4; i++) {
        int c = cg + i * 8;
        t[c][nl] = x[((size_t)b * CIN + c0 + c) * NPIX + n0 + nl];
    }
    __syncthreads();
    __half2 h0 = __floats2half2_rn(t[cg * 4 + 0][nl], t[cg * 4 + 1][nl]);
    __half2 h1 = __floats2half2_rn(t[cg * 4 + 2][nl], t[cg * 4 + 3][nl]);
    uint2 v;
    v.x = *(uint32_t*)&h0; v.y = *(uint32_t*)&h1;
    *(uint2*)(g_xT + ((size_t)b * NPIX + n0 + nl) * CIN + c0 + cg * 4) = v;
}

// ---------------- conv as implicit NT GEMM (fp16 mma, BM=64, BK=128) --------------
// k16-pipelined: fragments for step k16+1 prefetched during step k16's mma.
template <int COUT, int NTAPS>
__global__ __launch_bounds__(256, 2) void conv_mma_kernel(const float* __restrict__ bias_v) {
    extern __shared__ unsigned char smem[];
    uint32_t sb = smem_u32(smem);
    const uint32_t AB0 = sb, BB0 = sb + 32768;   // A: 2x16KB, B: 2x32KB

    int tid = threadIdx.x, lane = tid & 31, wid = tid >> 5;
    int wm = wid & 3, wn = wid >> 2;             // 4m x 2n over 64x128
    int b = blockIdx.z, m0 = blockIdx.y * 64, c0 = blockIdx.x * 128;

    const __half* xTb = g_xT + (size_t)b * NPIX * CIN;
    const __half* wb  = (NTAPS == 9) ? g_wvh : g_wkh;

    int lch = tid & 15;
    int ay[4], ax[4];
#pragma unroll
    for (int i = 0; i < 4; i++) {
        int row = (tid >> 4) + i * 16;
        int p = m0 + row;
        ay[i] = p / IMGW;
        ax[i] = p - ay[i] * IMGW;
    }

    const int NS = NTAPS * 2;
    auto load_stage = [&](int s, int buf) {
        int tap = (NTAPS == 9) ? (s >> 1) : 0;
        int kc  = s & 1;
        int dy = (NTAPS == 9) ? (tap / 3 - 1) : 0;
        int dx = (NTAPS == 9) ? (tap % 3 - 1) : 0;
        int off = dy * IMGW + dx;
        uint32_t ab = AB0 + buf * 16384, bb = BB0 + buf * 32768;
#pragma unroll
        for (int i = 0; i < 4; i++) {
            int row = (tid >> 4) + i * 16;
            bool valid = (NTAPS == 1) ||
                         (((unsigned)(ay[i] + dy) < (unsigned)IMGW) &&
                          ((unsigned)(ax[i] + dx) < (unsigned)IMGW));
            int srow = m0 + row + (valid ? off : 0);
            cpa16(ab + row * 256 + ((lch ^ (row & 7)) << 4),
                  xTb + (size_t)srow * CIN + kc * 128 + lch * 8, valid ? 16 : 0);
        }
#pragma unroll
        for (int i = 0; i < 8; i++) {
            int idx = tid + i * 256;
            int row = idx >> 4, ch = idx & 15;
            cpa16(bb + row * 256 + ((ch ^ (row & 7)) << 4),
                  wb + (size_t)(tap * COUT + c0 + row) * CIN + kc * 128 + ch * 8, 16);
        }
        CP_COMMIT();
    };

    float acc[8][4] = {};
    int arow  = wm * 16 + (lane & 15);
    int achp  = (lane >> 4);
    int bchp  = ((lane >> 3) & 1);
    int brow0 = (lane & 7) + ((lane >> 4) << 3);

    load_stage(0, 0);
    for (int s = 0; s < NS; s++) {
        if (s + 1 < NS) { load_stage(s + 1, (s + 1) & 1); CP_WAIT(1); }
        else            { CP_WAIT(0); }
        __syncthreads();
        uint32_t ab = AB0 + (s & 1) * 16384, bb = BB0 + (s & 1) * 32768;

        uint32_t afr[2][4], bfr[2][4][4];
        {
            int ch = achp;
            ldsm4(afr[0], ab + arow * 256 + ((ch ^ (arow & 7)) << 4));
#pragma unroll
            for (int np = 0; np < 4; np++) {
                int row = wn * 64 + np * 16 + brow0;
                ldsm4(bfr[0][np], bb + row * 256 + ((bchp ^ (row & 7)) << 4));
            }
        }
#pragma unroll
        for (int k16 = 0; k16 < 8; k16++) {
            int cur = k16 & 1, nx = cur ^ 1;
            if (k16 < 7) {
                int ch = (k16 + 1) * 2 + achp;
                ldsm4(afr[nx], ab + arow * 256 + ((ch ^ (arow & 7)) << 4));
#pragma unroll
                for (int np = 0; np < 4; np++) {
                    int row = wn * 64 + np * 16 + brow0;
                    int chb = (k16 + 1) * 2 + bchp;
                    ldsm4(bfr[nx][np], bb + row * 256 + ((chb ^ (row & 7)) << 4));
                }
            }
#pragma unroll
            for (int np = 0; np < 4; np++) {
                mma_f16(acc[2 * np],     afr[cur], bfr[cur][np][0], bfr[cur][np][1]);
                mma_f16(acc[2 * np + 1], afr[cur], bfr[cur][np][2], bfr[cur][np][3]);
            }
        }
        __syncthreads();
    }
    // epilogue: K scaled by sqrt(log2e) so S is natively in log2 domain
    int r0 = m0 + wm * 16 + (lane >> 2);
#pragma unroll
    for (int half = 0; half < 2; half++) {
        int rr = r0 + half * 8;
#pragma unroll
        for (int nt = 0; nt < 8; nt++) {
            int col = wn * 64 + nt * 8 + (lane & 3) * 2;
            float b0 = (NTAPS == 9) ? bias_v[c0 + col]     : g_kbias[c0 + col];
            float b1 = (NTAPS == 9) ? bias_v[c0 + col + 1] : g_kbias[c0 + col + 1];
            float v0 = acc[nt][half * 2] + b0;
            float v1 = acc[nt][half * 2 + 1] + b1;
            if (NTAPS == 1) {
                __half2 h = __floats2half2_rn(v0 * SQRT_LOG2E, v1 * SQRT_LOG2E);
                *(uint32_t*)(g_Kh + ((size_t)b * NPIX + rr) * COUT + c0 + col) = *(uint32_t*)&h;
            } else {
                __nv_bfloat162 h = __floats2bfloat162_rn(v0, v1);
                *(uint32_t*)(g_V + ((size_t)b * NPIX + rr) * COUT + c0 + col) = *(uint32_t*)&h;
            }
        }
    }
}

// ---------------- warp-specialized flash attention (ldsm-pipelined) ---------------
#define BFULL0 1
#define BEMPTY0 3
#define BSLOC 5
#define BPVLOC 6
__global__ __launch_bounds__(384) void flash_kernel() {
    extern __shared__ unsigned char smem[];
    const uint32_t sb = smem_u32(smem);
    const uint32_t KB0 = sb;                       // 2 x 32768
    const uint32_t VB0 = sb + 65536;               // 2 x 65536
    const uint32_t PB0 = sb + 65536 + 131072;      // 2 x 16384

    int tid = threadIdx.x, lane = tid & 31, wid = tid >> 5;
    int b = blockIdx.z, q0 = blockIdx.x * QT, split = blockIdx.y;
    int kbase = split * KCH;

    const __half* Kb = g_Kh + (size_t)b * NPIX * CK;
    const __nv_bfloat16* Vb = g_V + (size_t)b * NPIX * CV;

    if (wid < 4) {
        // ================= S-group (128 threads) =================
#pragma unroll
        for (int i = 0; i < 8; i++) {
            int idx = tid + i * 128;
            int row = idx >> 4, ch = idx & 15;
            cpa16(PB0 + row * 256 + ((ch ^ (row & 7)) << 4),
                  Kb + (size_t)(q0 + row) * CK + ch * 8, 16);
        }
        CP_COMMIT();
#pragma unroll
        for (int i = 0; i < 16; i++) {
            int idx = tid + i * 128;
            int row = idx >> 4, ch = idx & 15;
            cpa16(KB0 + row * 256 + ((ch ^ (row & 7)) << 4),
                  Kb + (size_t)(kbase + row) * CK + ch * 8, 16);
        }
        CP_COMMIT();
        CP_WAIT(1);
        bar_sync(BSLOC, 128);

        uint32_t aq[8][4];
        {
            int row = wid * 16 + (lane & 15);
#pragma unroll
            for (int k16 = 0; k16 < 8; k16++) {
                int ch = k16 * 2 + (lane >> 4);
                ldsm4(aq[k16], PB0 + row * 256 + ((ch ^ (row & 7)) << 4));
            }
        }

        int srow0 = (lane & 7) + ((lane >> 4) << 3);
        int schp  = ((lane >> 3) & 1);
        float ps0 = 0.f, ps1 = 0.f;
        for (int it = 0; it < NIT; it++) {
            int buf = it & 1;
            if (it + 1 < NIT) {
                bar_sync(BSLOC, 128);
#pragma unroll
                for (int i = 0; i < 16; i++) {
                    int idx = tid + i * 128;
                    int row = idx >> 4, ch = idx & 15;
                    cpa16(KB0 + (buf ^ 1) * 32768 + row * 256 + ((ch ^ (row & 7)) << 4),
                          Kb + (size_t)(kbase + (it + 1) * KT + row) * CK + ch * 8, 16);
                }
                CP_COMMIT();
                CP_WAIT(1);
            } else {
                CP_WAIT(0);
            }
            bar_sync(BSLOC, 128);

            uint32_t kb = KB0 + buf * 32768;
            float sacc[16][4] = {};
            uint32_t bqf[2][4];
            {
                ldsm4(bqf[0], kb + srow0 * 256 + ((schp ^ (srow0 & 7)) << 4));
            }
#pragma unroll
            for (int idx = 0; idx < 64; idx++) {
                int k16 = idx >> 3, np = idx & 7;
                int cur = idx & 1, nx = cur ^ 1;
                if (idx < 63) {
                    int k16n = (idx + 1) >> 3, npn = (idx + 1) & 7;
                    int row = npn * 16 + srow0;
                    int ch  = k16n * 2 + schp;
                    ldsm4(bqf[nx], kb + row * 256 + ((ch ^ (row & 7)) << 4));
                }
                mma_f16(sacc[2 * np],     aq[k16], bqf[cur][0], bqf[cur][1]);
                mma_f16(sacc[2 * np + 1], aq[k16], bqf[cur][2], bqf[cur][3]);
            }

            if (it >= 2) bar_sync(BEMPTY0 + buf, 384);   // PV consumed P buf (it-2)

            uint32_t pb = PB0 + buf * 16384;
            int prow0 = wid * 16 + (lane >> 2), prow1 = prow0 + 8;
            int cb = (lane & 3) * 4;
#pragma unroll
            for (int f = 0; f < 16; f++) {
                float* s = sacc[f];
                float e0 = ex2(s[0]), e1 = ex2(s[1]);
                float e2 = ex2(s[2]), e3 = ex2(s[3]);
                ps0 += e0 + e1;
                ps1 += e2 + e3;
                __nv_bfloat162 h0 = __floats2bfloat162_rn(e0, e1);
                __nv_bfloat162 h1 = __floats2bfloat162_rn(e2, e3);
                *(uint32_t*)(smem + (pb - sb) + prow0 * 256 + ((f ^ (prow0 & 7)) << 4) + cb) = *(uint32_t*)&h0;
                *(uint32_t*)(smem + (pb - sb) + prow1 * 256 + ((f ^ (prow1 & 7)) << 4) + cb) = *(uint32_t*)&h1;
            }
            bar_arrive(BFULL0 + buf, 384);
        }
        bar_sync(BEMPTY0 + ((NIT - 2) & 1), 384);
        bar_sync(BEMPTY0 + ((NIT - 1) & 1), 384);

        ps0 += __shfl_xor_sync(0xffffffff, ps0, 1);
        ps0 += __shfl_xor_sync(0xffffffff, ps0, 2);
        ps1 += __shfl_xor_sync(0xffffffff, ps1, 1);
        ps1 += __shfl_xor_sync(0xffffffff, ps1, 2);
        if ((lane & 3) == 0) {
            int base = (b * NSPLIT + split) * NPIX + q0 + wid * 16 + (lane >> 2);
            g_l[base]     = ps0;
            g_l[base + 8] = ps1;
        }
    } else {
        // ================= PV-group (256 threads) =================
        int pvtid = tid - 128;
        int pvid = wid - 4;
        int pm = pvid & 1, pc = pvid >> 1;

        auto load_v = [&](int it, int buf) {
#pragma unroll
            for (int i = 0; i < 16; i++) {
                int idx = pvtid + i * 256;
                int row = idx >> 5, ch = idx & 31;
                cpa16(VB0 + buf * 65536 + row * 512 + ((ch ^ (row & 7)) << 4),
                      Vb + (size_t)(kbase + it * KT + row) * CV + ch * 8, 16);
            }
            CP_COMMIT();
        };

        float acc[2][8][4] = {};
        int prowb = pm * 32 + (lane & 15);
        int krow0 = (lane & 7) + ((lane >> 3) & 1) * 8;
        int nchp  = pc * 8 + (lane >> 4);
        int achp  = (lane >> 4);

        load_v(0, 0);
        for (int it = 0; it < NIT; it++) {
            int buf = it & 1;
            if (it + 1 < NIT) {
                bar_sync(BPVLOC, 256);
                load_v(it + 1, buf ^ 1);
                CP_WAIT(1);
            } else {
                CP_WAIT(0);
            }
            bar_sync(BPVLOC, 256);
            bar_sync(BFULL0 + buf, 384);

            uint32_t pb = PB0 + buf * 16384, vb = VB0 + buf * 65536;
            uint32_t apf[2][2][4], bqf[2][4];
            {
                ldsm4(apf[0][0], pb + prowb * 256 + ((achp ^ (prowb & 7)) << 4));
                ldsm4(apf[0][1], pb + (prowb + 16) * 256 + ((achp ^ ((prowb + 16) & 7)) << 4));
                ldsm4t(bqf[0], vb + krow0 * 512 + ((nchp ^ (krow0 & 7)) << 4));
            }
#pragma unroll
            for (int idx = 0; idx < 32; idx++) {
                int k16 = idx >> 2, np = idx & 3;
                int cur = idx & 1, nx = cur ^ 1;
                int kc = k16 & 1, kn = kc ^ 1;
                if (np == 0 && k16 < 7) {
                    int ch = (k16 + 1) * 2 + achp;
                    ldsm4(apf[kn][0], pb + prowb * 256 + ((ch ^ (prowb & 7)) << 4));
                    ldsm4(apf[kn][1], pb + (prowb + 16) * 256 + ((ch ^ ((prowb + 16) & 7)) << 4));
                }
                if (idx < 31) {
                    int k16n = (idx + 1) >> 2, npn = (idx + 1) & 3;
                    int krow = k16n * 16 + krow0;
                    int nch  = npn * 2 + nchp;
                    ldsm4t(bqf[nx], vb + krow * 512 + ((nch ^ (krow & 7)) << 4));
                }
                mma_bf16(acc[0][2 * np],     apf[kc][0], bqf[cur][0], bqf[cur][1]);
                mma_bf16(acc[0][2 * np + 1], apf[kc][0], bqf[cur][2], bqf[cur][3]);
                mma_bf16(acc[1][2 * np],     apf[kc][1], bqf[cur][0], bqf[cur][1]);
                mma_bf16(acc[1][2 * np + 1], apf[kc][1], bqf[cur][2], bqf[cur][3]);
            }
            bar_arrive(BEMPTY0 + buf, 384);
        }

        float* op = g_part + ((size_t)(b * NSPLIT + split) * NPIX + q0) * CV;
#pragma unroll
        for (int mt = 0; mt < 2; mt++) {
            int r = pm * 32 + mt * 16 + (lane >> 2);
#pragma unroll
            for (int n8 = 0; n8 < 8; n8++) {
                int col = pc * 64 + n8 * 8 + (lane & 3) * 2;
                *(float2*)(op + (size_t)r * CV + col)       = make_float2(acc[mt][n8][0], acc[mt][n8][1]);
                *(float2*)(op + (size_t)(r + 8) * CV + col) = make_float2(acc[mt][n8][2], acc[mt][n8][3]);
            }
        }
    }
}

// ---------------- combine: ctx = (o0 + o1) / (l0 + l1) -> fp16 --------------------
__global__ void combine_kernel() {
    int idx = blockIdx.x * 4 + (threadIdx.x >> 6);
    int b = idx / NPIX, n = idx - b * NPIX;
    int c = (threadIdx.x & 63) * 4;
    float l0 = g_l[(b * NSPLIT + 0) * NPIX + n];
    float l1 = g_l[(b * NSPLIT + 1) * NPIX + n];
    float inv = 1.0f / (l0 + l1);
    const float* p0 = g_part + ((size_t)(b * NSPLIT + 0) * NPIX + n) * CV + c;
    const float* p1 = g_part + ((size_t)(b * NSPLIT + 1) * NPIX + n) * CV + c;
    float4 a = *(const float4*)p0;
    float4 bb = *(const float4*)p1;
    __half2 h0 = __floats2half2_rn((a.x + bb.x) * inv, (a.y + bb.y) * inv);
    __half2 h1 = __floats2half2_rn((a.z + bb.z) * inv, (a.w + bb.w) * inv);
    uint2 v;
    v.x = *(uint32_t*)&h0; v.y = *(uint32_t*)&h1;
    *(uint2*)(g_ctxh + ((size_t)b * NPIX + n) * CV + c) = v;
}

// ---------------- out[b][co][n] = ww @ ctx^T + bw + x (f16 mma) -------------------
__global__ __launch_bounds__(256) void gemm_out_kernel(const float* __restrict__ bw,
                                                       const float* __restrict__ x,
                                                       float* __restrict__ out) {
    extern __shared__ unsigned char smem[];
    uint32_t sb = smem_u32(smem);
    const uint32_t SA = sb, SB = sb + 65536;

    int tid = threadIdx.x, lane = tid & 31, wid = tid >> 5;
    int wm = wid & 3, wn = wid >> 2;
    int b = blockIdx.z, co0 = blockIdx.y * 128, n0 = blockIdx.x * 128;

#pragma unroll
    for (int i = 0; i < 16; i++) {
        int idx = tid + i * 256;
        int row = idx >> 5, ch = idx & 31;
        uint32_t soff = row * 512 + ((ch ^ (row & 7)) << 4);
        cpa16(SA + soff, g_wwh + (size_t)(co0 + row) * CV + ch * 8, 16);
        cpa16(SB + soff, g_ctxh + ((size_t)b * NPIX + n0 + row) * CV + ch * 8, 16);
    }
    CP_COMMIT();
    CP_WAIT(0);
    __syncthreads();

    float acc[2][8][4] = {};
#pragma unroll
    for (int k16 = 0; k16 < 16; k16++) {
        uint32_t a[2][4];
#pragma unroll
        for (int mt = 0; mt < 2; mt++) {
            int row = wm * 32 + mt * 16 + (lane & 15);
            int ch  = k16 * 2 + (lane >> 4);
            ldsm4(a[mt], SA + row * 512 + ((ch ^ (row & 7)) << 4));
        }
        uint32_t bq[4][4];
#pragma unroll
        for (int np = 0; np < 4; np++) {
            int row = wn * 64 + np * 16 + (lane & 7) + ((lane >> 4) << 3);
            int ch  = k16 * 2 + ((lane >> 3) & 1);
            ldsm4(bq[np], SB + row * 512 + ((ch ^ (row & 7)) << 4));
        }
#pragma unroll
        for (int mt = 0; mt < 2; mt++)
#pragma unroll
            for (int np = 0; np < 4; np++) {
                mma_f16(acc[mt][2 * np],     a[mt], bq[np][0], bq[np][1]);
                mma_f16(acc[mt][2 * np + 1], a[mt], bq[np][2], bq[np][3]);
            }
    }
#pragma unroll
    for (int mt = 0; mt < 2; mt++) {
#pragma unroll
        for (int half = 0; half < 2; half++) {
            int co = co0 + wm * 32 + mt * 16 + (lane >> 2) + half * 8;
            float bwv = bw[co];
            size_t xb = ((size_t)b * CIN + co) * NPIX + n0;
            size_t ob = ((size_t)b * CV  + co) * NPIX + n0;
#pragma unroll
            for (int n8 = 0; n8 < 8; n8++) {
                int col = wn * 64 + n8 * 8 + (lane & 3) * 2;
                float2 xv = *(const float2*)(x + xb + col);
                float2 o;
                o.x = acc[mt][n8][half * 2]     + bwv + xv.x;
                o.y = acc[mt][n8][half * 2 + 1] + bwv + xv.y;
                *(float2*)(out + ob + col) = o;
            }
        }
    }
}

// ---------------- launch ----------------------------------------------------------
extern "C" void kernel_launch(void* const* d_in, const int* in_sizes, int n_in,
                              void* d_out, int out_size) {
    (void)in_sizes; (void)n_in; (void)out_size;
    const float* x     = (const float*)d_in[0];
    const float* wk    = (const float*)d_in[1];
    const float* bk    = (const float*)d_in[2];
    const float* gamma = (const float*)d_in[3];
    const float* beta  = (const float*)d_in[4];
    const float* rmean = (const float*)d_in[5];
    const float* rvar  = (const float*)d_in[6];
    const float* wv    = (const float*)d_in[7];
    const float* bv    = (const float*)d_in[8];
    const float* ww    = (const float*)d_in[9];
    const float* bw    = (const float*)d_in[10];
    float* out = (float*)d_out;

    const int CONV_SMEM = 98304;
    const int OUT_SMEM = 131072;
    const int FLASH_SMEM = 65536 + 131072 + 32768;     // 229376
    cudaFuncSetAttribute(conv_mma_kernel<CK, 1>, cudaFuncAttributeMaxDynamicSharedMemorySize, CONV_SMEM);
    cudaFuncSetAttribute(conv_mma_kernel<CV, 9>, cudaFuncAttributeMaxDynamicSharedMemorySize, CONV_SMEM);
    cudaFuncSetAttribute(flash_kernel, cudaFuncAttributeMaxDynamicSharedMemorySize, FLASH_SMEM);
    cudaFuncSetAttribute(gemm_out_kernel, cudaFuncAttributeMaxDynamicSharedMemorySize, OUT_SMEM);

    prep_kernel<<<256, 256>>>(wk, bk, gamma, beta, rmean, rvar, wv, ww);
    transpose_x_kernel<<<dim3(NPIX / 32, CIN / 32, 2), 256>>>(x);
    conv_mma_kernel<CK, 1><<<dim3(1, NPIX / 64, 2), 256, CONV_SMEM>>>(bv);
    conv_mma_kernel<CV, 9><<<dim3(CV / 128, NPIX / 64, 2), 256, CONV_SMEM>>>(bv);
    flash_kernel<<<dim3(NPIX / QT, NSPLIT, 2), 384, FLASH_SMEM>>>();
    combine_kernel<<<2 * NPIX / 4, 256>>>();
    gemm_out_kernel<<<dim3(NPIX / 128, CV / 128, 2), 256, OUT_SMEM>>>(bw, x, out);
}